// round 1
// baseline (speedup 1.0000x reference)
#include <cuda_runtime.h>
#include <math.h>

#define NN 20000
#define EE 320000
#define ET (EE + NN)   // edges + self loops = 340000
#define GG 64

// ---------------- scratch (device globals; no runtime allocation) ----------
__device__ float g_h[NN * 256];      // per-layer transformed features [N, H*C]
__device__ float g_acc[NN * 256];    // per-layer aggregation accumulator
__device__ float g_asrc[NN * 4];
__device__ float g_adst[NN * 4];
__device__ float g_m[NN * 4];        // segment max
__device__ float g_den[NN * 4];      // segment sum of exp
__device__ float g_e[ET * 4];        // per-edge logits -> exp values
__device__ float g_x1[NN * 64];      // layer-1 output
__device__ float g_x2[NN * 32];      // layer-2 output
__device__ float g_sums[GG * 32];
__device__ float g_cnt[GG];

__device__ __forceinline__ float atomicMaxF(float* addr, float val) {
    int* ai = (int*)addr;
    int old = *ai;
    while (__int_as_float(old) < val) {
        int assumed = old;
        old = atomicCAS(ai, assumed, __float_as_int(val));
        if (old == assumed) break;
    }
    return __int_as_float(old);
}

// ---------------- generic kernels ----------------

__global__ void k_fill(float* p, int n, float v) {
    int i = blockIdx.x * blockDim.x + threadIdx.x;
    if (i < n) p[i] = v;
}

// C[n,m] = A[n,k] @ B[k,m]
__global__ void k_gemm(const float* __restrict__ A, const float* __restrict__ B,
                       float* __restrict__ C, int n, int k, int m) {
    int idx = blockIdx.x * blockDim.x + threadIdx.x;
    if (idx >= n * m) return;
    int row = idx / m, col = idx % m;
    const float* a = A + row * k;
    float s = 0.f;
#pragma unroll 8
    for (int i = 0; i < k; i++) s = fmaf(a[i], B[i * m + col], s);
    C[idx] = s;
}

// per-(node, head) attention coefficients
__global__ void k_att(const float* __restrict__ h, const float* __restrict__ as,
                      const float* __restrict__ ad, float* __restrict__ asrc,
                      float* __restrict__ adst, int n, int H, int C) {
    int idx = blockIdx.x * blockDim.x + threadIdx.x;
    if (idx >= n * H) return;
    int node = idx / H, hh = idx % H;
    const float* hp = h + (node * H + hh) * C;
    const float* sp = as + hh * C;
    const float* dp = ad + hh * C;
    float s = 0.f, d = 0.f;
    for (int c = 0; c < C; c++) { float v = hp[c]; s = fmaf(v, sp[c], s); d = fmaf(v, dp[c], d); }
    asrc[idx] = s;
    adst[idx] = d;
}

// pass 1: logits + segment max
__global__ void k_edge_max(const int* __restrict__ src, const int* __restrict__ dst,
                           const float* __restrict__ asrc, const float* __restrict__ adst,
                           float* __restrict__ ebuf, float* __restrict__ m, int H) {
    int idx = blockIdx.x * blockDim.x + threadIdx.x;
    if (idx >= ET * H) return;
    int e = idx / H, hh = idx % H;
    int s = (e < EE) ? src[e] : (e - EE);
    int d = (e < EE) ? dst[e] : (e - EE);
    float v = asrc[s * H + hh] + adst[d * H + hh];
    v = (v > 0.f) ? v : 0.2f * v;   // leaky relu
    ebuf[idx] = v;
    atomicMaxF(&m[d * H + hh], v);
}

// pass 2: exp + segment sum (denominator)
__global__ void k_edge_exp(const int* __restrict__ src, const int* __restrict__ dst,
                           float* __restrict__ ebuf, const float* __restrict__ m,
                           float* __restrict__ den, int H) {
    int idx = blockIdx.x * blockDim.x + threadIdx.x;
    if (idx >= ET * H) return;
    int e = idx / H, hh = idx % H;
    int d = (e < EE) ? dst[e] : (e - EE);
    float ee = expf(ebuf[idx] - m[d * H + hh]);
    ebuf[idx] = ee;
    atomicAdd(&den[d * H + hh], ee);
}

// pass 3: weighted scatter of h[src] into acc[dst]; consecutive threads cover
// one edge's H*C contiguous channels -> coalesced gather + contiguous RED.ADD
__global__ void k_edge_scatter(const int* __restrict__ src, const int* __restrict__ dst,
                               const float* __restrict__ ebuf, const float* __restrict__ h,
                               float* __restrict__ acc, int H, int C) {
    int HC = H * C;
    long long idx = (long long)blockIdx.x * blockDim.x + threadIdx.x;
    if (idx >= (long long)ET * HC) return;
    int e = (int)(idx / HC);
    int r = (int)(idx % HC);
    int hh = r / C;
    int s = (e < EE) ? src[e] : (e - EE);
    int d = (e < EE) ? dst[e] : (e - EE);
    atomicAdd(&acc[(long long)d * HC + r], h[(long long)s * HC + r] * ebuf[e * H + hh]);
}

// per-node: normalize by denom, mean over heads, + bias, relu
__global__ void k_finalize(const float* __restrict__ acc, const float* __restrict__ den,
                           const float* __restrict__ bias, float* __restrict__ out,
                           int n, int H, int C) {
    int idx = blockIdx.x * blockDim.x + threadIdx.x;
    if (idx >= n * C) return;
    int node = idx / C, c = idx % C;
    float s = 0.f;
    for (int hh = 0; hh < H; hh++)
        s += acc[(node * H + hh) * C + c] / (den[node * H + hh] + 1e-16f);
    s = s / (float)H + bias[c];
    out[idx] = (s > 0.f) ? s : 0.f;
}

// global mean pool (accumulate)
__global__ void k_pool(const float* __restrict__ x, const int* __restrict__ batch,
                       float* __restrict__ sums, float* __restrict__ cnt) {
    int idx = blockIdx.x * blockDim.x + threadIdx.x;
    if (idx >= NN * 32) return;
    int node = idx / 32, c = idx % 32;
    int g = batch[node];
    atomicAdd(&sums[g * 32 + c], x[idx]);
    if (c == 0) atomicAdd(&cnt[g], 1.f);
}

// MLP heads: one thread per graph. out[0:64]=halt, out[64:128]=cont
__global__ void k_heads(const float* __restrict__ sums, const float* __restrict__ cnt,
                        const float* __restrict__ cW1, const float* __restrict__ cb1,
                        const float* __restrict__ cW2, const float* __restrict__ cb2,
                        const float* __restrict__ hW1, const float* __restrict__ hb1,
                        const float* __restrict__ hW2, const float* __restrict__ hb2,
                        float* __restrict__ out) {
    int g = threadIdx.x;
    if (g >= GG) return;
    float emb[32];
    float c_ = cnt[g];
    c_ = (c_ > 1.f) ? c_ : 1.f;
    for (int c = 0; c < 32; c++) emb[c] = sums[g * 32 + c] / c_;
    float oh = hb2[0], oc = cb2[0];
    for (int j = 0; j < 16; j++) {
        float sh = hb1[j], sc = cb1[j];
        for (int c = 0; c < 32; c++) {
            sh = fmaf(emb[c], hW1[c * 16 + j], sh);
            sc = fmaf(emb[c], cW1[c * 16 + j], sc);
        }
        sh = (sh > 0.f) ? sh : 0.f;
        sc = (sc > 0.f) ? sc : 0.f;
        oh = fmaf(sh, hW2[j], oh);
        oc = fmaf(sc, cW2[j], oc);
    }
    out[g]      = 1.f / (1.f + expf(-oh));   // halt
    out[GG + g] = 1.f / (1.f + expf(-oc));   // cont
}

// ---------------- host launch ----------------

static inline int cdiv(long long a, int b) { return (int)((a + b - 1) / b); }

static void run_gat_layer(const int* src, const int* dst,
                          const float* x_in, int Fin,
                          const float* W, const float* as, const float* ad,
                          const float* bias, int H, int C, float* x_out,
                          float* p_h, float* p_acc, float* p_asrc, float* p_adst,
                          float* p_m, float* p_den, float* p_e) {
    const int T = 256;
    int HC = H * C;
    // h = x @ W
    k_gemm<<<cdiv((long long)NN * HC, T), T>>>(x_in, W, p_h, NN, Fin, HC);
    // attention coefficients
    k_att<<<cdiv((long long)NN * H, T), T>>>(p_h, as, ad, p_asrc, p_adst, NN, H, C);
    // init reductions
    k_fill<<<cdiv((long long)NN * H, T), T>>>(p_m, NN * H, -1e30f);
    k_fill<<<cdiv((long long)NN * H, T), T>>>(p_den, NN * H, 0.f);
    k_fill<<<cdiv((long long)NN * HC, T), T>>>(p_acc, NN * HC, 0.f);
    // segment softmax + aggregate
    k_edge_max<<<cdiv((long long)ET * H, T), T>>>(src, dst, p_asrc, p_adst, p_e, p_m, H);
    k_edge_exp<<<cdiv((long long)ET * H, T), T>>>(src, dst, p_e, p_m, p_den, H);
    k_edge_scatter<<<cdiv((long long)ET * HC, T), T>>>(src, dst, p_e, p_h, p_acc, H, C);
    k_finalize<<<cdiv((long long)NN * C, T), T>>>(p_acc, p_den, bias, x_out, NN, H, C);
}

extern "C" void kernel_launch(void* const* d_in, const int* in_sizes, int n_in,
                              void* d_out, int out_size) {
    const float* x     = (const float*)d_in[0];
    const int*   ei    = (const int*)  d_in[1];   // [2, E]
    const int*   batch = (const int*)  d_in[2];
    const float* W1  = (const float*)d_in[3];
    const float* as1 = (const float*)d_in[4];
    const float* ad1 = (const float*)d_in[5];
    const float* b1  = (const float*)d_in[6];
    const float* W2  = (const float*)d_in[7];
    const float* as2 = (const float*)d_in[8];
    const float* ad2 = (const float*)d_in[9];
    const float* b2  = (const float*)d_in[10];
    const float* cW1 = (const float*)d_in[11];
    const float* cb1 = (const float*)d_in[12];
    const float* cW2 = (const float*)d_in[13];
    const float* cb2 = (const float*)d_in[14];
    const float* hW1 = (const float*)d_in[15];
    const float* hb1 = (const float*)d_in[16];
    const float* hW2 = (const float*)d_in[17];
    const float* hb2 = (const float*)d_in[18];

    const int* src = ei;
    const int* dst = ei + EE;

    float *p_h, *p_acc, *p_asrc, *p_adst, *p_m, *p_den, *p_e, *p_x1, *p_x2, *p_sums, *p_cnt;
    cudaGetSymbolAddress((void**)&p_h, g_h);
    cudaGetSymbolAddress((void**)&p_acc, g_acc);
    cudaGetSymbolAddress((void**)&p_asrc, g_asrc);
    cudaGetSymbolAddress((void**)&p_adst, g_adst);
    cudaGetSymbolAddress((void**)&p_m, g_m);
    cudaGetSymbolAddress((void**)&p_den, g_den);
    cudaGetSymbolAddress((void**)&p_e, g_e);
    cudaGetSymbolAddress((void**)&p_x1, g_x1);
    cudaGetSymbolAddress((void**)&p_x2, g_x2);
    cudaGetSymbolAddress((void**)&p_sums, g_sums);
    cudaGetSymbolAddress((void**)&p_cnt, g_cnt);

    const int T = 256;

    // Layer 1: IN=128 -> H=4, C=64, relu
    run_gat_layer(src, dst, x, 128, W1, as1, ad1, b1, 4, 64, p_x1,
                  p_h, p_acc, p_asrc, p_adst, p_m, p_den, p_e);
    // Layer 2: 64 -> H=2, C=32, relu
    run_gat_layer(src, dst, p_x1, 64, W2, as2, ad2, b2, 2, 32, p_x2,
                  p_h, p_acc, p_asrc, p_adst, p_m, p_den, p_e);

    // global mean pool
    k_fill<<<cdiv(GG * 32, T), T>>>(p_sums, GG * 32, 0.f);
    k_fill<<<1, GG>>>(p_cnt, GG, 0.f);
    k_pool<<<cdiv((long long)NN * 32, T), T>>>(p_x2, batch, p_sums, p_cnt);

    // MLP heads
    k_heads<<<1, 64>>>(p_sums, p_cnt, cW1, cb1, cW2, cb2, hW1, hb1, hW2, hb2,
                       (float*)d_out);
}

// round 2
// speedup vs baseline: 2.8027x; 2.8027x over previous
#include <cuda_runtime.h>
#include <math.h>

#define NN 20000
#define EE 320000
#define ET (EE + NN)   // edges + self loops
#define GG 64

// ---------------- scratch (device globals) ----------------
__device__ float g_h[NN * 256];      // transformed features [N, H*C]
__device__ float g_x1[NN * 64];
__device__ float g_x2[NN * 32];
__device__ float g_asrc[NN * 4];
__device__ float g_adst[NN * 4];
__device__ int   g_cnt[NN];
__device__ int   g_off[NN + 1];
__device__ int   g_cur[NN];
__device__ int   g_csr[ET];          // src node per sorted-by-dst edge slot
__device__ float g_sums[GG * 32];
__device__ float g_gcnt[GG];

__device__ __forceinline__ float lrelu(float v) { return v > 0.f ? v : 0.2f * v; }

__device__ __forceinline__ float warp_max(float v) {
#pragma unroll
    for (int o = 16; o > 0; o >>= 1) v = fmaxf(v, __shfl_xor_sync(0xffffffff, v, o));
    return v;
}
__device__ __forceinline__ float warp_sum(float v) {
#pragma unroll
    for (int o = 16; o > 0; o >>= 1) v += __shfl_xor_sync(0xffffffff, v, o);
    return v;
}

// ---------------- CSR build ----------------
__global__ void k_zero_int(int* p, int n) {
    int i = blockIdx.x * blockDim.x + threadIdx.x;
    if (i < n) p[i] = 0;
}
__global__ void k_zero_f(float* p, int n) {
    int i = blockIdx.x * blockDim.x + threadIdx.x;
    if (i < n) p[i] = 0.f;
}
__global__ void k_count(const int* __restrict__ dst, int* __restrict__ cnt) {
    int e = blockIdx.x * blockDim.x + threadIdx.x;
    if (e >= ET) return;
    int d = (e < EE) ? dst[e] : (e - EE);
    atomicAdd(&cnt[d], 1);
}
// single-block exclusive scan over NN counters -> off, cur
__global__ void k_scan(const int* __restrict__ cnt, int* __restrict__ off,
                       int* __restrict__ cur) {
    __shared__ int ssum[1024];
    const int CH = 20;   // 1024*20 >= NN
    int t = threadIdx.x;
    int base = t * CH;
    int local[CH];
    int s = 0;
#pragma unroll
    for (int j = 0; j < CH; j++) {
        int v = (base + j < NN) ? cnt[base + j] : 0;
        local[j] = s;
        s += v;
    }
    ssum[t] = s;
    __syncthreads();
    for (int o = 1; o < 1024; o <<= 1) {
        int v = (t >= o) ? ssum[t - o] : 0;
        __syncthreads();
        ssum[t] += v;
        __syncthreads();
    }
    int pre = ssum[t] - s;   // exclusive prefix of this chunk
#pragma unroll
    for (int j = 0; j < CH; j++) {
        if (base + j < NN) { off[base + j] = pre + local[j]; cur[base + j] = pre + local[j]; }
    }
    if (t == 1023) off[NN] = ssum[1023];
}
__global__ void k_build(const int* __restrict__ src, const int* __restrict__ dst,
                        int* __restrict__ cur, int* __restrict__ csr) {
    int e = blockIdx.x * blockDim.x + threadIdx.x;
    if (e >= ET) return;
    int s = (e < EE) ? src[e] : (e - EE);
    int d = (e < EE) ? dst[e] : (e - EE);
    int pos = atomicAdd(&cur[d], 1);
    csr[pos] = s;
}

// ---------------- GEMM: C[n,M] = A[n,K] @ B[K,M], 4 cols per thread --------
template <int K, int M>
__global__ void k_gemm4(const float* __restrict__ A, const float* __restrict__ B,
                        float* __restrict__ C, int n) {
    int idx = blockIdx.x * blockDim.x + threadIdx.x;
    const int MG = M / 4;
    if (idx >= n * MG) return;
    int row = idx / MG, cg = idx % MG;
    const float4* B4 = (const float4*)B;
    const float4* A4 = (const float4*)(A + (long long)row * K);
    float4 acc = make_float4(0.f, 0.f, 0.f, 0.f);
#pragma unroll 8
    for (int i = 0; i < K / 4; i++) {
        float4 a = A4[i];
        float4 b0 = B4[(4 * i + 0) * MG + cg];
        float4 b1 = B4[(4 * i + 1) * MG + cg];
        float4 b2 = B4[(4 * i + 2) * MG + cg];
        float4 b3 = B4[(4 * i + 3) * MG + cg];
        acc.x = fmaf(a.x, b0.x, acc.x); acc.y = fmaf(a.x, b0.y, acc.y);
        acc.z = fmaf(a.x, b0.z, acc.z); acc.w = fmaf(a.x, b0.w, acc.w);
        acc.x = fmaf(a.y, b1.x, acc.x); acc.y = fmaf(a.y, b1.y, acc.y);
        acc.z = fmaf(a.y, b1.z, acc.z); acc.w = fmaf(a.y, b1.w, acc.w);
        acc.x = fmaf(a.z, b2.x, acc.x); acc.y = fmaf(a.z, b2.y, acc.y);
        acc.z = fmaf(a.z, b2.z, acc.z); acc.w = fmaf(a.z, b2.w, acc.w);
        acc.x = fmaf(a.w, b3.x, acc.x); acc.y = fmaf(a.w, b3.y, acc.y);
        acc.z = fmaf(a.w, b3.z, acc.z); acc.w = fmaf(a.w, b3.w, acc.w);
    }
    ((float4*)C)[idx] = acc;
}

// ---------------- per-(node,head) attention coefficients ----------------
template <int H, int C>
__global__ void k_att(const float* __restrict__ h, const float* __restrict__ as,
                      const float* __restrict__ ad, float* __restrict__ asrc,
                      float* __restrict__ adst) {
    int idx = blockIdx.x * blockDim.x + threadIdx.x;
    if (idx >= NN * H) return;
    int node = idx / H, hh = idx % H;
    const float4* hp = (const float4*)(h + ((long long)node * H + hh) * C);
    const float4* sp = (const float4*)(as + hh * C);
    const float4* dp = (const float4*)(ad + hh * C);
    float s = 0.f, d = 0.f;
#pragma unroll
    for (int c = 0; c < C / 4; c++) {
        float4 v = hp[c], a = sp[c], b = dp[c];
        s = fmaf(v.x, a.x, fmaf(v.y, a.y, fmaf(v.z, a.z, fmaf(v.w, a.w, s))));
        d = fmaf(v.x, b.x, fmaf(v.y, b.y, fmaf(v.z, b.z, fmaf(v.w, b.w, d))));
    }
    asrc[idx] = s;
    adst[idx] = d;
}

// ---------------- layer 1 aggregation: warp per node, H=4, C=64 ------------
__global__ void k_agg1(const int* __restrict__ off, const int* __restrict__ csr,
                       const float* __restrict__ hfeat, const float* __restrict__ asrc,
                       const float* __restrict__ adst, const float* __restrict__ bias,
                       float* __restrict__ out) {
    int warp = (blockIdx.x * blockDim.x + threadIdx.x) >> 5;
    if (warp >= NN) return;
    int lane = threadIdx.x & 31;
    int d = warp;
    int b0 = off[d], b1 = off[d + 1];

    float ad0 = adst[d * 4 + 0], ad1 = adst[d * 4 + 1];
    float ad2 = adst[d * 4 + 2], ad3 = adst[d * 4 + 3];

    // pass 1: per-head max
    float m0 = -1e30f, m1 = -1e30f, m2 = -1e30f, m3 = -1e30f;
    for (int k = b0 + lane; k < b1; k += 32) {
        int s = csr[k];
        m0 = fmaxf(m0, lrelu(asrc[s * 4 + 0] + ad0));
        m1 = fmaxf(m1, lrelu(asrc[s * 4 + 1] + ad1));
        m2 = fmaxf(m2, lrelu(asrc[s * 4 + 2] + ad2));
        m3 = fmaxf(m3, lrelu(asrc[s * 4 + 3] + ad3));
    }
    m0 = warp_max(m0); m1 = warp_max(m1); m2 = warp_max(m2); m3 = warp_max(m3);

    // pass 2: denominators
    float s0 = 0.f, s1 = 0.f, s2 = 0.f, s3 = 0.f;
    for (int k = b0 + lane; k < b1; k += 32) {
        int s = csr[k];
        s0 += __expf(lrelu(asrc[s * 4 + 0] + ad0) - m0);
        s1 += __expf(lrelu(asrc[s * 4 + 1] + ad1) - m1);
        s2 += __expf(lrelu(asrc[s * 4 + 2] + ad2) - m2);
        s3 += __expf(lrelu(asrc[s * 4 + 3] + ad3) - m3);
    }
    s0 = warp_sum(s0); s1 = warp_sum(s1); s2 = warp_sum(s2); s3 = warp_sum(s3);
    float i0 = 1.f / (s0 + 1e-16f), i1 = 1.f / (s1 + 1e-16f);
    float i2 = 1.f / (s2 + 1e-16f), i3 = 1.f / (s3 + 1e-16f);

    // pass 3: weighted gather. lane holds channels 4L..4L+3 (head L>>4) and
    // 128+4L.. (head 2+(L>>4)).
    int hA = lane >> 4;                 // 0 or 1
    float mA  = hA ? m1 : m0,  mB  = hA ? m3 : m2;
    float iA  = hA ? i1 : i0,  iB  = hA ? i3 : i2;
    float adA = hA ? ad1 : ad0, adB = hA ? ad3 : ad2;
    float4 acc0 = make_float4(0.f, 0.f, 0.f, 0.f);
    float4 acc1 = make_float4(0.f, 0.f, 0.f, 0.f);
    const float4* hf4 = (const float4*)hfeat;
    for (int k = b0; k < b1; k++) {
        int s = csr[k];
        float wA = __expf(lrelu(asrc[s * 4 + hA]     + adA) - mA) * iA;
        float wB = __expf(lrelu(asrc[s * 4 + 2 + hA] + adB) - mB) * iB;
        float4 v0 = hf4[(long long)s * 64 + lane];
        float4 v1 = hf4[(long long)s * 64 + 32 + lane];
        acc0.x = fmaf(wA, v0.x, acc0.x); acc0.y = fmaf(wA, v0.y, acc0.y);
        acc0.z = fmaf(wA, v0.z, acc0.z); acc0.w = fmaf(wA, v0.w, acc0.w);
        acc1.x = fmaf(wB, v1.x, acc1.x); acc1.y = fmaf(wB, v1.y, acc1.y);
        acc1.z = fmaf(wB, v1.z, acc1.z); acc1.w = fmaf(wB, v1.w, acc1.w);
    }
    // combine heads: t = (hA heads) ; xor 16 adds the other pair
    float4 t = make_float4(acc0.x + acc1.x, acc0.y + acc1.y,
                           acc0.z + acc1.z, acc0.w + acc1.w);
    t.x += __shfl_xor_sync(0xffffffff, t.x, 16);
    t.y += __shfl_xor_sync(0xffffffff, t.y, 16);
    t.z += __shfl_xor_sync(0xffffffff, t.z, 16);
    t.w += __shfl_xor_sync(0xffffffff, t.w, 16);
    if (lane < 16) {
        const float4 b = ((const float4*)bias)[lane];
        float4 o;
        o.x = fmaxf(t.x * 0.25f + b.x, 0.f);
        o.y = fmaxf(t.y * 0.25f + b.y, 0.f);
        o.z = fmaxf(t.z * 0.25f + b.z, 0.f);
        o.w = fmaxf(t.w * 0.25f + b.w, 0.f);
        ((float4*)out)[d * 16 + lane] = o;
    }
}

// ---------------- layer 2 aggregation: warp per node, H=2, C=32 ------------
__global__ void k_agg2(const int* __restrict__ off, const int* __restrict__ csr,
                       const float* __restrict__ hfeat, const float* __restrict__ asrc,
                       const float* __restrict__ adst, const float* __restrict__ bias,
                       float* __restrict__ out) {
    int warp = (blockIdx.x * blockDim.x + threadIdx.x) >> 5;
    if (warp >= NN) return;
    int lane = threadIdx.x & 31;
    int d = warp;
    int b0 = off[d], b1 = off[d + 1];

    float ad0 = adst[d * 2 + 0], ad1 = adst[d * 2 + 1];

    float m0 = -1e30f, m1 = -1e30f;
    for (int k = b0 + lane; k < b1; k += 32) {
        int s = csr[k];
        m0 = fmaxf(m0, lrelu(asrc[s * 2 + 0] + ad0));
        m1 = fmaxf(m1, lrelu(asrc[s * 2 + 1] + ad1));
    }
    m0 = warp_max(m0); m1 = warp_max(m1);

    float s0 = 0.f, s1 = 0.f;
    for (int k = b0 + lane; k < b1; k += 32) {
        int s = csr[k];
        s0 += __expf(lrelu(asrc[s * 2 + 0] + ad0) - m0);
        s1 += __expf(lrelu(asrc[s * 2 + 1] + ad1) - m1);
    }
    s0 = warp_sum(s0); s1 = warp_sum(s1);
    float i0 = 1.f / (s0 + 1e-16f), i1 = 1.f / (s1 + 1e-16f);

    // lane holds channels 2L..2L+1 (head L>>4)
    int hh = lane >> 4;
    float mH = hh ? m1 : m0, iH = hh ? i1 : i0, adH = hh ? ad1 : ad0;
    float2 acc = make_float2(0.f, 0.f);
    const float2* hf2 = (const float2*)hfeat;
    for (int k = b0; k < b1; k++) {
        int s = csr[k];
        float w = __expf(lrelu(asrc[s * 2 + hh] + adH) - mH) * iH;
        float2 v = hf2[(long long)s * 32 + lane];
        acc.x = fmaf(w, v.x, acc.x);
        acc.y = fmaf(w, v.y, acc.y);
    }
    acc.x += __shfl_xor_sync(0xffffffff, acc.x, 16);
    acc.y += __shfl_xor_sync(0xffffffff, acc.y, 16);
    if (lane < 16) {
        const float2 b = ((const float2*)bias)[lane];
        float2 o;
        o.x = fmaxf(acc.x * 0.5f + b.x, 0.f);
        o.y = fmaxf(acc.y * 0.5f + b.y, 0.f);
        ((float2*)out)[d * 16 + lane] = o;
    }
}

// ---------------- pooling + heads ----------------
__global__ void k_pool(const float* __restrict__ x, const int* __restrict__ batch,
                       float* __restrict__ sums, float* __restrict__ cnt) {
    int idx = blockIdx.x * blockDim.x + threadIdx.x;
    if (idx >= NN * 32) return;
    int node = idx / 32, c = idx % 32;
    int g = batch[node];
    atomicAdd(&sums[g * 32 + c], x[idx]);
    if (c == 0) atomicAdd(&cnt[g], 1.f);
}

__global__ void k_heads(const float* __restrict__ sums, const float* __restrict__ cnt,
                        const float* __restrict__ cW1, const float* __restrict__ cb1,
                        const float* __restrict__ cW2, const float* __restrict__ cb2,
                        const float* __restrict__ hW1, const float* __restrict__ hb1,
                        const float* __restrict__ hW2, const float* __restrict__ hb2,
                        float* __restrict__ out) {
    int g = threadIdx.x;
    if (g >= GG) return;
    float emb[32];
    float c_ = cnt[g];
    c_ = (c_ > 1.f) ? c_ : 1.f;
    for (int c = 0; c < 32; c++) emb[c] = sums[g * 32 + c] / c_;
    float oh = hb2[0], oc = cb2[0];
    for (int j = 0; j < 16; j++) {
        float sh = hb1[j], sc = cb1[j];
        for (int c = 0; c < 32; c++) {
            sh = fmaf(emb[c], hW1[c * 16 + j], sh);
            sc = fmaf(emb[c], cW1[c * 16 + j], sc);
        }
        sh = fmaxf(sh, 0.f);
        sc = fmaxf(sc, 0.f);
        oh = fmaf(sh, hW2[j], oh);
        oc = fmaf(sc, cW2[j], oc);
    }
    out[g]      = 1.f / (1.f + __expf(-oh));
    out[GG + g] = 1.f / (1.f + __expf(-oc));
}

// ---------------- host ----------------
static inline int cdiv(long long a, int b) { return (int)((a + b - 1) / b); }

extern "C" void kernel_launch(void* const* d_in, const int* in_sizes, int n_in,
                              void* d_out, int out_size) {
    const float* x     = (const float*)d_in[0];
    const int*   ei    = (const int*)  d_in[1];
    const int*   batch = (const int*)  d_in[2];
    const float* W1  = (const float*)d_in[3];
    const float* as1 = (const float*)d_in[4];
    const float* ad1 = (const float*)d_in[5];
    const float* b1  = (const float*)d_in[6];
    const float* W2  = (const float*)d_in[7];
    const float* as2 = (const float*)d_in[8];
    const float* ad2 = (const float*)d_in[9];
    const float* b2  = (const float*)d_in[10];
    const float* cW1 = (const float*)d_in[11];
    const float* cb1 = (const float*)d_in[12];
    const float* cW2 = (const float*)d_in[13];
    const float* cb2 = (const float*)d_in[14];
    const float* hW1 = (const float*)d_in[15];
    const float* hb1 = (const float*)d_in[16];
    const float* hW2 = (const float*)d_in[17];
    const float* hb2 = (const float*)d_in[18];

    const int* src = ei;
    const int* dst = ei + EE;

    float *p_h, *p_x1, *p_x2, *p_asrc, *p_adst, *p_sums, *p_gcnt;
    int *p_cnt, *p_off, *p_cur, *p_csr;
    cudaGetSymbolAddress((void**)&p_h, g_h);
    cudaGetSymbolAddress((void**)&p_x1, g_x1);
    cudaGetSymbolAddress((void**)&p_x2, g_x2);
    cudaGetSymbolAddress((void**)&p_asrc, g_asrc);
    cudaGetSymbolAddress((void**)&p_adst, g_adst);
    cudaGetSymbolAddress((void**)&p_cnt, g_cnt);
    cudaGetSymbolAddress((void**)&p_off, g_off);
    cudaGetSymbolAddress((void**)&p_cur, g_cur);
    cudaGetSymbolAddress((void**)&p_csr, g_csr);
    cudaGetSymbolAddress((void**)&p_sums, g_sums);
    cudaGetSymbolAddress((void**)&p_gcnt, g_gcnt);

    const int T = 256;

    // CSR build (dst-sorted)
    k_zero_int<<<cdiv(NN, T), T>>>(p_cnt, NN);
    k_count<<<cdiv(ET, T), T>>>(dst, p_cnt);
    k_scan<<<1, 1024>>>(p_cnt, p_off, p_cur);
    k_build<<<cdiv(ET, T), T>>>(src, dst, p_cur, p_csr);

    // Layer 1: 128 -> (4 heads x 64), head-mean, relu
    k_gemm4<128, 256><<<cdiv((long long)NN * 64, T), T>>>(x, W1, p_h, NN);
    k_att<4, 64><<<cdiv(NN * 4, T), T>>>(p_h, as1, ad1, p_asrc, p_adst);
    k_agg1<<<cdiv((long long)NN * 32, T), T>>>(p_off, p_csr, p_h, p_asrc, p_adst, b1, p_x1);

    // Layer 2: 64 -> (2 heads x 32), head-mean, relu
    k_gemm4<64, 64><<<cdiv((long long)NN * 16, T), T>>>(p_x1, W2, p_h, NN);
    k_att<2, 32><<<cdiv(NN * 2, T), T>>>(p_h, as2, ad2, p_asrc, p_adst);
    k_agg2<<<cdiv((long long)NN * 32, T), T>>>(p_off, p_csr, p_h, p_asrc, p_adst, b2, p_x2);

    // Pool + heads
    k_zero_f<<<cdiv(GG * 32 + GG, T), T>>>(p_sums, GG * 32 + GG);  // sums then gcnt? separate:
    k_zero_f<<<1, GG>>>(p_gcnt, GG);
    k_pool<<<cdiv((long long)NN * 32, T), T>>>(p_x2, batch, p_sums, p_gcnt);
    k_heads<<<1, GG>>>(p_sums, p_gcnt, cW1, cb1, cW2, cb2, hW1, hb1, hW2, hb2,
                       (float*)d_out);
}

// round 3
// speedup vs baseline: 3.3592x; 1.1986x over previous
#include <cuda_runtime.h>
#include <math.h>

#define NN 20000
#define EE 320000
#define ET (EE + NN)
#define GG 64
#define FULL 0xffffffffu

// ---------------- scratch ----------------
__device__ float g_h[NN * 256];      // layer-1 transformed features [N,256]; reused as h2 [N,64]
__device__ float g_h2[NN * 64];      // layer-2 transformed features
__device__ float g_asrc[NN * 4];
__device__ float g_adst[NN * 4];
__device__ float g_asrc2[NN * 2];
__device__ float g_adst2[NN * 2];
__device__ int   g_cnt[NN];
__device__ int   g_off[NN + 1];
__device__ int   g_cur[NN];
__device__ int   g_csr[ET];
__device__ float g_sums[GG * 32];
__device__ float g_gcnt[GG];

__device__ __forceinline__ float lrelu(float v) { return v > 0.f ? v : 0.2f * v; }
__device__ __forceinline__ float warp_sum(float v) {
#pragma unroll
    for (int o = 16; o > 0; o >>= 1) v += __shfl_xor_sync(FULL, v, o);
    return v;
}

// ---------------- CSR build ----------------
__global__ void k_count(const int* __restrict__ dst, int* __restrict__ cnt) {
    int e = blockIdx.x * blockDim.x + threadIdx.x;
    if (e >= ET) return;
    int d = (e < EE) ? dst[e] : (e - EE);
    atomicAdd(&cnt[d], 1);
}

__global__ void k_scan(const int* __restrict__ cnt, int* __restrict__ off,
                       int* __restrict__ cur, float* __restrict__ sums,
                       float* __restrict__ gcnt) {
    __shared__ int ssum[1024];
    const int CH = 20;
    int t = threadIdx.x;
    // zero pooling buffers (runs before agg2 in-stream)
    sums[t] = 0.f; sums[t + 1024] = 0.f;
    if (t < GG) gcnt[t] = 0.f;
    int base = t * CH;
    int local[CH];
    int s = 0;
#pragma unroll
    for (int j = 0; j < CH; j++) {
        int v = (base + j < NN) ? cnt[base + j] : 0;
        local[j] = s;
        s += v;
    }
    ssum[t] = s;
    __syncthreads();
    for (int o = 1; o < 1024; o <<= 1) {
        int v = (t >= o) ? ssum[t - o] : 0;
        __syncthreads();
        ssum[t] += v;
        __syncthreads();
    }
    int pre = ssum[t] - s;
#pragma unroll
    for (int j = 0; j < CH; j++) {
        if (base + j < NN) { off[base + j] = pre + local[j]; cur[base + j] = pre + local[j]; }
    }
    if (t == 1023) off[NN] = ssum[1023];
}

__global__ void k_build(const int* __restrict__ src, const int* __restrict__ dst,
                        int* __restrict__ cur, int* __restrict__ csr) {
    int e = blockIdx.x * blockDim.x + threadIdx.x;
    if (e >= ET) return;
    int s = (e < EE) ? src[e] : (e - EE);
    int d = (e < EE) ? dst[e] : (e - EE);
    int pos = atomicAdd(&cur[d], 1);
    csr[pos] = s;
}

// ---------------- GEMM1 (128->256) fused with att1 coefficients ------------
__global__ void k_gemm1(const float* __restrict__ A, const float* __restrict__ B,
                        const float* __restrict__ as1, const float* __restrict__ ad1,
                        float* __restrict__ C, float* __restrict__ asrc,
                        float* __restrict__ adst) {
    int idx = blockIdx.x * blockDim.x + threadIdx.x;   // NN*64 threads
    int row = idx >> 6, cg = idx & 63;                  // 4 channels per thread
    const float4* A4 = (const float4*)(A + (long long)row * 128);
    const float4* B4 = (const float4*)B;                // [128][64] float4 groups
    float4 acc = make_float4(0.f, 0.f, 0.f, 0.f);
#pragma unroll 8
    for (int i = 0; i < 32; i++) {
        float4 a = A4[i];
        float4 b0 = B4[(4 * i + 0) * 64 + cg];
        float4 b1 = B4[(4 * i + 1) * 64 + cg];
        float4 b2 = B4[(4 * i + 2) * 64 + cg];
        float4 b3 = B4[(4 * i + 3) * 64 + cg];
        acc.x = fmaf(a.x, b0.x, acc.x); acc.y = fmaf(a.x, b0.y, acc.y);
        acc.z = fmaf(a.x, b0.z, acc.z); acc.w = fmaf(a.x, b0.w, acc.w);
        acc.x = fmaf(a.y, b1.x, acc.x); acc.y = fmaf(a.y, b1.y, acc.y);
        acc.z = fmaf(a.y, b1.z, acc.z); acc.w = fmaf(a.y, b1.w, acc.w);
        acc.x = fmaf(a.z, b2.x, acc.x); acc.y = fmaf(a.z, b2.y, acc.y);
        acc.z = fmaf(a.z, b2.z, acc.z); acc.w = fmaf(a.z, b2.w, acc.w);
        acc.x = fmaf(a.w, b3.x, acc.x); acc.y = fmaf(a.w, b3.y, acc.y);
        acc.z = fmaf(a.w, b3.z, acc.z); acc.w = fmaf(a.w, b3.w, acc.w);
    }
    ((float4*)C)[idx] = acc;
    // fused attention coefficients: head = cg>>4, channels (cg&15)*4..+3
    float4 av = ((const float4*)as1)[cg];
    float4 dv = ((const float4*)ad1)[cg];
    float s = acc.x * av.x + acc.y * av.y + acc.z * av.z + acc.w * av.w;
    float d = acc.x * dv.x + acc.y * dv.y + acc.z * dv.z + acc.w * dv.w;
#pragma unroll
    for (int o = 1; o < 16; o <<= 1) {
        s += __shfl_xor_sync(FULL, s, o);
        d += __shfl_xor_sync(FULL, d, o);
    }
    if ((cg & 15) == 0) {
        asrc[row * 4 + (cg >> 4)] = s;
        adst[row * 4 + (cg >> 4)] = d;
    }
}

// ---------------- layer 1 aggregation + fused GEMM2 + att2 ----------------
__global__ void k_agg1(const int* __restrict__ off, const int* __restrict__ csr,
                       const float* __restrict__ hfeat, const float* __restrict__ asrc,
                       const float* __restrict__ adst, const float* __restrict__ bias,
                       const float* __restrict__ W2, const float* __restrict__ as2,
                       const float* __restrict__ ad2, float* __restrict__ h2out,
                       float* __restrict__ asrc2, float* __restrict__ adst2) {
    int warp = (blockIdx.x * blockDim.x + threadIdx.x) >> 5;
    if (warp >= NN) return;
    int lane = threadIdx.x & 31;
    int d = warp;
    int b0 = off[d], b1 = off[d + 1];

    float ad0 = adst[d * 4 + 0], ad1 = adst[d * 4 + 1];
    float ad2_ = adst[d * 4 + 2], ad3 = adst[d * 4 + 3];

    // denominators (no max-shift: logits are small; softmax is shift-invariant)
    float s0 = 0.f, s1 = 0.f, s2 = 0.f, s3 = 0.f;
    for (int k = b0 + lane; k < b1; k += 32) {
        int s = csr[k];
        float4 a = ((const float4*)asrc)[s];
        s0 += __expf(lrelu(a.x + ad0));
        s1 += __expf(lrelu(a.y + ad1));
        s2 += __expf(lrelu(a.z + ad2_));
        s3 += __expf(lrelu(a.w + ad3));
    }
    s0 = warp_sum(s0); s1 = warp_sum(s1); s2 = warp_sum(s2); s3 = warp_sum(s3);
    float i0 = 1.f / (s0 + 1e-16f), i1 = 1.f / (s1 + 1e-16f);
    float i2 = 1.f / (s2 + 1e-16f), i3 = 1.f / (s3 + 1e-16f);

    // weighted gather: lane covers channels 4*(lane&15)+j of heads (lane>>4) and 2+(lane>>4)
    int hA = lane >> 4;
    float iA  = hA ? i1 : i0,  iB  = hA ? i3 : i2;
    float adA = hA ? ad1 : ad0, adB = hA ? ad3 : ad2_;
    float4 acc0 = make_float4(0.f, 0.f, 0.f, 0.f);
    float4 acc1 = make_float4(0.f, 0.f, 0.f, 0.f);
    const float4* hf4 = (const float4*)hfeat;
#pragma unroll 4
    for (int k = b0; k < b1; k++) {
        int s = csr[k];
        float wA = __expf(lrelu(asrc[s * 4 + hA]     + adA)) * iA;
        float wB = __expf(lrelu(asrc[s * 4 + 2 + hA] + adB)) * iB;
        float4 v0 = hf4[(long long)s * 64 + lane];
        float4 v1 = hf4[(long long)s * 64 + 32 + lane];
        acc0.x = fmaf(wA, v0.x, acc0.x); acc0.y = fmaf(wA, v0.y, acc0.y);
        acc0.z = fmaf(wA, v0.z, acc0.z); acc0.w = fmaf(wA, v0.w, acc0.w);
        acc1.x = fmaf(wB, v1.x, acc1.x); acc1.y = fmaf(wB, v1.y, acc1.y);
        acc1.z = fmaf(wB, v1.z, acc1.z); acc1.w = fmaf(wB, v1.w, acc1.w);
    }
    float4 t = make_float4(acc0.x + acc1.x, acc0.y + acc1.y,
                           acc0.z + acc1.z, acc0.w + acc1.w);
    t.x += __shfl_xor_sync(FULL, t.x, 16);   // after xor16 all lanes hold the sum
    t.y += __shfl_xor_sync(FULL, t.y, 16);
    t.z += __shfl_xor_sync(FULL, t.z, 16);
    t.w += __shfl_xor_sync(FULL, t.w, 16);

    // x1[4*(lane&15)+j] = relu(t/4 + bias)
    const float4 bb = ((const float4*)bias)[lane & 15];
    float4 xv;
    xv.x = fmaxf(t.x * 0.25f + bb.x, 0.f);
    xv.y = fmaxf(t.y * 0.25f + bb.y, 0.f);
    xv.z = fmaxf(t.z * 0.25f + bb.z, 0.f);
    xv.w = fmaxf(t.w * 0.25f + bb.w, 0.f);

    // fused GEMM2: h2[c] = sum_k x1[k]*W2[k*64+c]; lane computes c=2*lane, 2*lane+1
    const float2* W2f2 = (const float2*)W2;
    float2 h2 = make_float2(0.f, 0.f);
#pragma unroll
    for (int g = 0; g < 16; g++) {
        float vx = __shfl_sync(FULL, xv.x, g);
        float vy = __shfl_sync(FULL, xv.y, g);
        float vz = __shfl_sync(FULL, xv.z, g);
        float vw = __shfl_sync(FULL, xv.w, g);
        float2 w0 = W2f2[(g * 4 + 0) * 32 + lane];
        float2 w1 = W2f2[(g * 4 + 1) * 32 + lane];
        float2 w2 = W2f2[(g * 4 + 2) * 32 + lane];
        float2 w3 = W2f2[(g * 4 + 3) * 32 + lane];
        h2.x = fmaf(vx, w0.x, h2.x); h2.y = fmaf(vx, w0.y, h2.y);
        h2.x = fmaf(vy, w1.x, h2.x); h2.y = fmaf(vy, w1.y, h2.y);
        h2.x = fmaf(vz, w2.x, h2.x); h2.y = fmaf(vz, w2.y, h2.y);
        h2.x = fmaf(vw, w3.x, h2.x); h2.y = fmaf(vw, w3.y, h2.y);
    }
    ((float2*)h2out)[d * 32 + lane] = h2;

    // fused att2: head = lane>>4, channels 2*(lane&15)+{0,1}
    float2 a2 = ((const float2*)as2)[lane];
    float2 d2 = ((const float2*)ad2)[lane];
    float ps = h2.x * a2.x + h2.y * a2.y;
    float pd = h2.x * d2.x + h2.y * d2.y;
#pragma unroll
    for (int o = 1; o < 16; o <<= 1) {
        ps += __shfl_xor_sync(FULL, ps, o);
        pd += __shfl_xor_sync(FULL, pd, o);
    }
    if ((lane & 15) == 0) {
        asrc2[d * 2 + hA] = ps;
        adst2[d * 2 + hA] = pd;
    }
}

// ---------------- layer 2 aggregation + fused global mean pool -------------
__global__ void k_agg2(const int* __restrict__ off, const int* __restrict__ csr,
                       const float* __restrict__ hfeat, const float* __restrict__ asrc,
                       const float* __restrict__ adst, const float* __restrict__ bias,
                       const int* __restrict__ batch, float* __restrict__ sums,
                       float* __restrict__ gcnt) {
    int warp = (blockIdx.x * blockDim.x + threadIdx.x) >> 5;
    if (warp >= NN) return;
    int lane = threadIdx.x & 31;
    int d = warp;
    int b0 = off[d], b1 = off[d + 1];

    float ad0 = adst[d * 2 + 0], ad1 = adst[d * 2 + 1];

    float s0 = 0.f, s1 = 0.f;
    for (int k = b0 + lane; k < b1; k += 32) {
        int s = csr[k];
        float2 a = ((const float2*)asrc)[s];
        s0 += __expf(lrelu(a.x + ad0));
        s1 += __expf(lrelu(a.y + ad1));
    }
    s0 = warp_sum(s0); s1 = warp_sum(s1);
    float i0 = 1.f / (s0 + 1e-16f), i1 = 1.f / (s1 + 1e-16f);

    int hh = lane >> 4;
    float iH = hh ? i1 : i0, adH = hh ? ad1 : ad0;
    float2 acc = make_float2(0.f, 0.f);
    const float2* hf2 = (const float2*)hfeat;
#pragma unroll 4
    for (int k = b0; k < b1; k++) {
        int s = csr[k];
        float w = __expf(lrelu(asrc[s * 2 + hh] + adH)) * iH;
        float2 v = hf2[(long long)s * 32 + lane];
        acc.x = fmaf(w, v.x, acc.x);
        acc.y = fmaf(w, v.y, acc.y);
    }
    acc.x += __shfl_xor_sync(FULL, acc.x, 16);
    acc.y += __shfl_xor_sync(FULL, acc.y, 16);
    if (lane < 16) {
        const float2 b = ((const float2*)bias)[lane];
        float ox = fmaxf(acc.x * 0.5f + b.x, 0.f);
        float oy = fmaxf(acc.y * 0.5f + b.y, 0.f);
        int g = batch[d];
        atomicAdd(&sums[g * 32 + 2 * lane], ox);
        atomicAdd(&sums[g * 32 + 2 * lane + 1], oy);
        if (lane == 0) atomicAdd(&gcnt[g], 1.f);
    }
}

// ---------------- heads ----------------
__global__ void k_heads(const float* __restrict__ sums, const float* __restrict__ cnt,
                        const float* __restrict__ cW1, const float* __restrict__ cb1,
                        const float* __restrict__ cW2, const float* __restrict__ cb2,
                        const float* __restrict__ hW1, const float* __restrict__ hb1,
                        const float* __restrict__ hW2, const float* __restrict__ hb2,
                        float* __restrict__ out) {
    int g = threadIdx.x;
    if (g >= GG) return;
    float emb[32];
    float c_ = cnt[g];
    c_ = (c_ > 1.f) ? c_ : 1.f;
    for (int c = 0; c < 32; c++) emb[c] = sums[g * 32 + c] / c_;
    float oh = hb2[0], oc = cb2[0];
    for (int j = 0; j < 16; j++) {
        float sh = hb1[j], sc = cb1[j];
        for (int c = 0; c < 32; c++) {
            sh = fmaf(emb[c], hW1[c * 16 + j], sh);
            sc = fmaf(emb[c], cW1[c * 16 + j], sc);
        }
        sh = fmaxf(sh, 0.f);
        sc = fmaxf(sc, 0.f);
        oh = fmaf(sh, hW2[j], oh);
        oc = fmaf(sc, cW2[j], oc);
    }
    out[g]      = 1.f / (1.f + __expf(-oh));
    out[GG + g] = 1.f / (1.f + __expf(-oc));
}

// ---------------- host ----------------
static inline int cdiv(long long a, int b) { return (int)((a + b - 1) / b); }

extern "C" void kernel_launch(void* const* d_in, const int* in_sizes, int n_in,
                              void* d_out, int out_size) {
    const float* x     = (const float*)d_in[0];
    const int*   ei    = (const int*)  d_in[1];
    const int*   batch = (const int*)  d_in[2];
    const float* W1  = (const float*)d_in[3];
    const float* as1 = (const float*)d_in[4];
    const float* ad1 = (const float*)d_in[5];
    const float* b1  = (const float*)d_in[6];
    const float* W2  = (const float*)d_in[7];
    const float* as2 = (const float*)d_in[8];
    const float* ad2 = (const float*)d_in[9];
    const float* b2  = (const float*)d_in[10];
    const float* cW1 = (const float*)d_in[11];
    const float* cb1 = (const float*)d_in[12];
    const float* cW2 = (const float*)d_in[13];
    const float* cb2 = (const float*)d_in[14];
    const float* hW1 = (const float*)d_in[15];
    const float* hb1 = (const float*)d_in[16];
    const float* hW2 = (const float*)d_in[17];
    const float* hb2 = (const float*)d_in[18];

    const int* src = ei;
    const int* dst = ei + EE;

    float *p_h, *p_h2, *p_asrc, *p_adst, *p_asrc2, *p_adst2, *p_sums, *p_gcnt;
    int *p_cnt, *p_off, *p_cur, *p_csr;
    cudaGetSymbolAddress((void**)&p_h, g_h);
    cudaGetSymbolAddress((void**)&p_h2, g_h2);
    cudaGetSymbolAddress((void**)&p_asrc, g_asrc);
    cudaGetSymbolAddress((void**)&p_adst, g_adst);
    cudaGetSymbolAddress((void**)&p_asrc2, g_asrc2);
    cudaGetSymbolAddress((void**)&p_adst2, g_adst2);
    cudaGetSymbolAddress((void**)&p_cnt, g_cnt);
    cudaGetSymbolAddress((void**)&p_off, g_off);
    cudaGetSymbolAddress((void**)&p_cur, g_cur);
    cudaGetSymbolAddress((void**)&p_csr, g_csr);
    cudaGetSymbolAddress((void**)&p_sums, g_sums);
    cudaGetSymbolAddress((void**)&p_gcnt, g_gcnt);

    const int T = 256;

    // CSR build (dst-sorted)
    cudaMemsetAsync(p_cnt, 0, NN * sizeof(int));
    k_count<<<cdiv(ET, T), T>>>(dst, p_cnt);
    k_scan<<<1, 1024>>>(p_cnt, p_off, p_cur, p_sums, p_gcnt);
    k_build<<<cdiv(ET, T), T>>>(src, dst, p_cur, p_csr);

    // Layer 1 GEMM + att coefficients
    k_gemm1<<<cdiv((long long)NN * 64, T), T>>>(x, W1, as1, ad1, p_h, p_asrc, p_adst);
    // Layer 1 aggregation + fused layer-2 GEMM + att2
    k_agg1<<<cdiv((long long)NN * 32, T), T>>>(p_off, p_csr, p_h, p_asrc, p_adst, b1,
                                               W2, as2, ad2, p_h2, p_asrc2, p_adst2);
    // Layer 2 aggregation + fused mean pool
    k_agg2<<<cdiv((long long)NN * 32, T), T>>>(p_off, p_csr, p_h2, p_asrc2, p_adst2, b2,
                                               batch, p_sums, p_gcnt);
    // Heads
    k_heads<<<1, GG>>>(p_sums, p_gcnt, cW1, cb1, cW2, cb2, hW1, hb1, hW2, hb2,
                       (float*)d_out);
}

// round 4
// speedup vs baseline: 4.1972x; 1.2495x over previous
#include <cuda_runtime.h>
#include <math.h>

#define NN 20000
#define EE 320000
#define ET (EE + NN)
#define GG 64
#define FULL 0xffffffffu

// ---------------- scratch ----------------
__device__ float g_h[NN * 256];
__device__ float g_h2[NN * 64];
__device__ float g_asrc[NN * 4];
__device__ float g_adst[NN * 4];
__device__ float g_asrc2[NN * 2];
__device__ float g_adst2[NN * 2];
__device__ int   g_cnt[NN];
__device__ int   g_off[NN + 1];
__device__ int   g_cur[NN];
__device__ int   g_csr[ET];
__device__ float g_sums[GG * 32];
__device__ float g_gcnt[GG];

__device__ __forceinline__ float lrelu(float v) { return v > 0.f ? v : 0.2f * v; }
__device__ __forceinline__ float warp_sum(float v) {
#pragma unroll
    for (int o = 16; o > 0; o >>= 1) v += __shfl_xor_sync(FULL, v, o);
    return v;
}

// ---------------- CSR build ----------------
__global__ void k_count(const int* __restrict__ dst, int* __restrict__ cnt) {
    int e = blockIdx.x * blockDim.x + threadIdx.x;
    if (e >= ET) return;
    int d = (e < EE) ? dst[e] : (e - EE);
    atomicAdd(&cnt[d], 1);
}

__global__ void k_scan(const int* __restrict__ cnt, int* __restrict__ off,
                       int* __restrict__ cur, float* __restrict__ sums,
                       float* __restrict__ gcnt) {
    __shared__ int ssum[1024];
    const int CH = 20;
    int t = threadIdx.x;
    sums[t] = 0.f; sums[t + 1024] = 0.f;
    if (t < GG) gcnt[t] = 0.f;
    int base = t * CH;
    int local[CH];
    int s = 0;
#pragma unroll
    for (int j = 0; j < CH; j++) {
        int v = (base + j < NN) ? cnt[base + j] : 0;
        local[j] = s;
        s += v;
    }
    ssum[t] = s;
    __syncthreads();
    for (int o = 1; o < 1024; o <<= 1) {
        int v = (t >= o) ? ssum[t - o] : 0;
        __syncthreads();
        ssum[t] += v;
        __syncthreads();
    }
    int pre = ssum[t] - s;
#pragma unroll
    for (int j = 0; j < CH; j++) {
        if (base + j < NN) { off[base + j] = pre + local[j]; cur[base + j] = pre + local[j]; }
    }
    if (t == 1023) off[NN] = ssum[1023];
}

__global__ void k_build(const int* __restrict__ src, const int* __restrict__ dst,
                        int* __restrict__ cur, int* __restrict__ csr) {
    int e = blockIdx.x * blockDim.x + threadIdx.x;
    if (e >= ET) return;
    int s = (e < EE) ? src[e] : (e - EE);
    int d = (e < EE) ? dst[e] : (e - EE);
    int pos = atomicAdd(&cur[d], 1);
    csr[pos] = s;
}

// ---------------- GEMM1 (128->256), 4 rows x 4 cols per thread + att1 ------
// One warp handles a 4-row x 128-col strip. All lanes share the 4 A rows
// (broadcast loads); each B load is reused across 4 rows.
__global__ void k_gemm1(const float* __restrict__ A, const float* __restrict__ B,
                        const float* __restrict__ as1, const float* __restrict__ ad1,
                        float* __restrict__ C, float* __restrict__ asrc,
                        float* __restrict__ adst) {
    int gw = (blockIdx.x * blockDim.x + threadIdx.x) >> 5;
    int lane = threadIdx.x & 31;
    int strip = gw >> 1;
    if (strip >= NN / 4) return;
    int half = gw & 1;
    int cg = half * 32 + lane;          // col group 0..63 (4 cols each)
    int row0 = strip * 4;

    const float4* A4 = (const float4*)A;    // [NN][32]
    const float4* B4 = (const float4*)B;    // [128][64]

    float4 c0 = make_float4(0.f,0.f,0.f,0.f);
    float4 c1 = make_float4(0.f,0.f,0.f,0.f);
    float4 c2 = make_float4(0.f,0.f,0.f,0.f);
    float4 c3 = make_float4(0.f,0.f,0.f,0.f);

#pragma unroll 4
    for (int i = 0; i < 32; i++) {
        float4 b0 = B4[(4 * i + 0) * 64 + cg];
        float4 b1 = B4[(4 * i + 1) * 64 + cg];
        float4 b2 = B4[(4 * i + 2) * 64 + cg];
        float4 b3 = B4[(4 * i + 3) * 64 + cg];
        float4 a;
        a = A4[(row0 + 0) * 32 + i];
        c0.x = fmaf(a.x,b0.x,c0.x); c0.y = fmaf(a.x,b0.y,c0.y); c0.z = fmaf(a.x,b0.z,c0.z); c0.w = fmaf(a.x,b0.w,c0.w);
        c0.x = fmaf(a.y,b1.x,c0.x); c0.y = fmaf(a.y,b1.y,c0.y); c0.z = fmaf(a.y,b1.z,c0.z); c0.w = fmaf(a.y,b1.w,c0.w);
        c0.x = fmaf(a.z,b2.x,c0.x); c0.y = fmaf(a.z,b2.y,c0.y); c0.z = fmaf(a.z,b2.z,c0.z); c0.w = fmaf(a.z,b2.w,c0.w);
        c0.x = fmaf(a.w,b3.x,c0.x); c0.y = fmaf(a.w,b3.y,c0.y); c0.z = fmaf(a.w,b3.z,c0.z); c0.w = fmaf(a.w,b3.w,c0.w);
        a = A4[(row0 + 1) * 32 + i];
        c1.x = fmaf(a.x,b0.x,c1.x); c1.y = fmaf(a.x,b0.y,c1.y); c1.z = fmaf(a.x,b0.z,c1.z); c1.w = fmaf(a.x,b0.w,c1.w);
        c1.x = fmaf(a.y,b1.x,c1.x); c1.y = fmaf(a.y,b1.y,c1.y); c1.z = fmaf(a.y,b1.z,c1.z); c1.w = fmaf(a.y,b1.w,c1.w);
        c1.x = fmaf(a.z,b2.x,c1.x); c1.y = fmaf(a.z,b2.y,c1.y); c1.z = fmaf(a.z,b2.z,c1.z); c1.w = fmaf(a.z,b2.w,c1.w);
        c1.x = fmaf(a.w,b3.x,c1.x); c1.y = fmaf(a.w,b3.y,c1.y); c1.z = fmaf(a.w,b3.z,c1.z); c1.w = fmaf(a.w,b3.w,c1.w);
        a = A4[(row0 + 2) * 32 + i];
        c2.x = fmaf(a.x,b0.x,c2.x); c2.y = fmaf(a.x,b0.y,c2.y); c2.z = fmaf(a.x,b0.z,c2.z); c2.w = fmaf(a.x,b0.w,c2.w);
        c2.x = fmaf(a.y,b1.x,c2.x); c2.y = fmaf(a.y,b1.y,c2.y); c2.z = fmaf(a.y,b1.z,c2.z); c2.w = fmaf(a.y,b1.w,c2.w);
        c2.x = fmaf(a.z,b2.x,c2.x); c2.y = fmaf(a.z,b2.y,c2.y); c2.z = fmaf(a.z,b2.z,c2.z); c2.w = fmaf(a.z,b2.w,c2.w);
        c2.x = fmaf(a.w,b3.x,c2.x); c2.y = fmaf(a.w,b3.y,c2.y); c2.z = fmaf(a.w,b3.z,c2.z); c2.w = fmaf(a.w,b3.w,c2.w);
        a = A4[(row0 + 3) * 32 + i];
        c3.x = fmaf(a.x,b0.x,c3.x); c3.y = fmaf(a.x,b0.y,c3.y); c3.z = fmaf(a.x,b0.z,c3.z); c3.w = fmaf(a.x,b0.w,c3.w);
        c3.x = fmaf(a.y,b1.x,c3.x); c3.y = fmaf(a.y,b1.y,c3.y); c3.z = fmaf(a.y,b1.z,c3.z); c3.w = fmaf(a.y,b1.w,c3.w);
        c3.x = fmaf(a.z,b2.x,c3.x); c3.y = fmaf(a.z,b2.y,c3.y); c3.z = fmaf(a.z,b2.z,c3.z); c3.w = fmaf(a.z,b2.w,c3.w);
        c3.x = fmaf(a.w,b3.x,c3.x); c3.y = fmaf(a.w,b3.y,c3.y); c3.z = fmaf(a.w,b3.z,c3.z); c3.w = fmaf(a.w,b3.w,c3.w);
    }

    float4* C4 = (float4*)C;
    C4[(row0 + 0) * 64 + cg] = c0;
    C4[(row0 + 1) * 64 + cg] = c1;
    C4[(row0 + 2) * 64 + cg] = c2;
    C4[(row0 + 3) * 64 + cg] = c3;

    // fused att1: head = cg>>4 (constant within each 16-lane group)
    float4 av = ((const float4*)as1)[cg];
    float4 dv = ((const float4*)ad1)[cg];
    float s0 = c0.x*av.x + c0.y*av.y + c0.z*av.z + c0.w*av.w;
    float s1 = c1.x*av.x + c1.y*av.y + c1.z*av.z + c1.w*av.w;
    float s2 = c2.x*av.x + c2.y*av.y + c2.z*av.z + c2.w*av.w;
    float s3 = c3.x*av.x + c3.y*av.y + c3.z*av.z + c3.w*av.w;
    float d0 = c0.x*dv.x + c0.y*dv.y + c0.z*dv.z + c0.w*dv.w;
    float d1 = c1.x*dv.x + c1.y*dv.y + c1.z*dv.z + c1.w*dv.w;
    float d2 = c2.x*dv.x + c2.y*dv.y + c2.z*dv.z + c2.w*dv.w;
    float d3 = c3.x*dv.x + c3.y*dv.y + c3.z*dv.z + c3.w*dv.w;
#pragma unroll
    for (int o = 1; o < 16; o <<= 1) {
        s0 += __shfl_xor_sync(FULL, s0, o); d0 += __shfl_xor_sync(FULL, d0, o);
        s1 += __shfl_xor_sync(FULL, s1, o); d1 += __shfl_xor_sync(FULL, d1, o);
        s2 += __shfl_xor_sync(FULL, s2, o); d2 += __shfl_xor_sync(FULL, d2, o);
        s3 += __shfl_xor_sync(FULL, s3, o); d3 += __shfl_xor_sync(FULL, d3, o);
    }
    if ((lane & 15) == 0) {
        int head = cg >> 4;                  // 0..3
        asrc[(row0 + 0) * 4 + head] = s0; adst[(row0 + 0) * 4 + head] = d0;
        asrc[(row0 + 1) * 4 + head] = s1; adst[(row0 + 1) * 4 + head] = d1;
        asrc[(row0 + 2) * 4 + head] = s2; adst[(row0 + 2) * 4 + head] = d2;
        asrc[(row0 + 3) * 4 + head] = s3; adst[(row0 + 3) * 4 + head] = d3;
    }
}

// ---------------- layer 1 aggregation + fused GEMM2 + att2 ----------------
__global__ void k_agg1(const int* __restrict__ off, const int* __restrict__ csr,
                       const float* __restrict__ hfeat, const float* __restrict__ asrc,
                       const float* __restrict__ adst, const float* __restrict__ bias,
                       const float* __restrict__ W2, const float* __restrict__ as2,
                       const float* __restrict__ ad2, float* __restrict__ h2out,
                       float* __restrict__ asrc2, float* __restrict__ adst2) {
    int warp = (blockIdx.x * blockDim.x + threadIdx.x) >> 5;
    if (warp >= NN) return;
    int lane = threadIdx.x & 31;
    int d = warp;
    int b0 = off[d], b1 = off[d + 1];

    float ad0 = adst[d * 4 + 0], ad1 = adst[d * 4 + 1];
    float ad2_ = adst[d * 4 + 2], ad3 = adst[d * 4 + 3];

    float s0 = 0.f, s1 = 0.f, s2 = 0.f, s3 = 0.f;
    for (int k = b0 + lane; k < b1; k += 32) {
        int s = csr[k];
        float4 a = ((const float4*)asrc)[s];
        s0 += __expf(lrelu(a.x + ad0));
        s1 += __expf(lrelu(a.y + ad1));
        s2 += __expf(lrelu(a.z + ad2_));
        s3 += __expf(lrelu(a.w + ad3));
    }
    s0 = warp_sum(s0); s1 = warp_sum(s1); s2 = warp_sum(s2); s3 = warp_sum(s3);
    float i0 = 1.f / (s0 + 1e-16f), i1 = 1.f / (s1 + 1e-16f);
    float i2 = 1.f / (s2 + 1e-16f), i3 = 1.f / (s3 + 1e-16f);

    int hA = lane >> 4;
    float iA  = hA ? i1 : i0,  iB  = hA ? i3 : i2;
    float adA = hA ? ad1 : ad0, adB = hA ? ad3 : ad2_;
    float4 acc0 = make_float4(0.f, 0.f, 0.f, 0.f);
    float4 acc1 = make_float4(0.f, 0.f, 0.f, 0.f);
    const float4* hf4 = (const float4*)hfeat;
#pragma unroll 4
    for (int k = b0; k < b1; k++) {
        int s = csr[k];
        float wA = __expf(lrelu(asrc[s * 4 + hA]     + adA)) * iA;
        float wB = __expf(lrelu(asrc[s * 4 + 2 + hA] + adB)) * iB;
        float4 v0 = hf4[(long long)s * 64 + lane];
        float4 v1 = hf4[(long long)s * 64 + 32 + lane];
        acc0.x = fmaf(wA, v0.x, acc0.x); acc0.y = fmaf(wA, v0.y, acc0.y);
        acc0.z = fmaf(wA, v0.z, acc0.z); acc0.w = fmaf(wA, v0.w, acc0.w);
        acc1.x = fmaf(wB, v1.x, acc1.x); acc1.y = fmaf(wB, v1.y, acc1.y);
        acc1.z = fmaf(wB, v1.z, acc1.z); acc1.w = fmaf(wB, v1.w, acc1.w);
    }
    float4 t = make_float4(acc0.x + acc1.x, acc0.y + acc1.y,
                           acc0.z + acc1.z, acc0.w + acc1.w);
    t.x += __shfl_xor_sync(FULL, t.x, 16);
    t.y += __shfl_xor_sync(FULL, t.y, 16);
    t.z += __shfl_xor_sync(FULL, t.z, 16);
    t.w += __shfl_xor_sync(FULL, t.w, 16);

    const float4 bb = ((const float4*)bias)[lane & 15];
    float4 xv;
    xv.x = fmaxf(t.x * 0.25f + bb.x, 0.f);
    xv.y = fmaxf(t.y * 0.25f + bb.y, 0.f);
    xv.z = fmaxf(t.z * 0.25f + bb.z, 0.f);
    xv.w = fmaxf(t.w * 0.25f + bb.w, 0.f);

    const float2* W2f2 = (const float2*)W2;
    float2 h2 = make_float2(0.f, 0.f);
#pragma unroll
    for (int g = 0; g < 16; g++) {
        float vx = __shfl_sync(FULL, xv.x, g);
        float vy = __shfl_sync(FULL, xv.y, g);
        float vz = __shfl_sync(FULL, xv.z, g);
        float vw = __shfl_sync(FULL, xv.w, g);
        float2 w0 = W2f2[(g * 4 + 0) * 32 + lane];
        float2 w1 = W2f2[(g * 4 + 1) * 32 + lane];
        float2 w2 = W2f2[(g * 4 + 2) * 32 + lane];
        float2 w3 = W2f2[(g * 4 + 3) * 32 + lane];
        h2.x = fmaf(vx, w0.x, h2.x); h2.y = fmaf(vx, w0.y, h2.y);
        h2.x = fmaf(vy, w1.x, h2.x); h2.y = fmaf(vy, w1.y, h2.y);
        h2.x = fmaf(vz, w2.x, h2.x); h2.y = fmaf(vz, w2.y, h2.y);
        h2.x = fmaf(vw, w3.x, h2.x); h2.y = fmaf(vw, w3.y, h2.y);
    }
    ((float2*)h2out)[d * 32 + lane] = h2;

    float2 a2 = ((const float2*)as2)[lane];
    float2 d2 = ((const float2*)ad2)[lane];
    float ps = h2.x * a2.x + h2.y * a2.y;
    float pd = h2.x * d2.x + h2.y * d2.y;
#pragma unroll
    for (int o = 1; o < 16; o <<= 1) {
        ps += __shfl_xor_sync(FULL, ps, o);
        pd += __shfl_xor_sync(FULL, pd, o);
    }
    if ((lane & 15) == 0) {
        asrc2[d * 2 + hA] = ps;
        adst2[d * 2 + hA] = pd;
    }
}

// ---------------- layer 2 aggregation + fused global mean pool -------------
__global__ void k_agg2(const int* __restrict__ off, const int* __restrict__ csr,
                       const float* __restrict__ hfeat, const float* __restrict__ asrc,
                       const float* __restrict__ adst, const float* __restrict__ bias,
                       const int* __restrict__ batch, float* __restrict__ sums,
                       float* __restrict__ gcnt) {
    int warp = (blockIdx.x * blockDim.x + threadIdx.x) >> 5;
    if (warp >= NN) return;
    int lane = threadIdx.x & 31;
    int d = warp;
    int b0 = off[d], b1 = off[d + 1];

    float ad0 = adst[d * 2 + 0], ad1 = adst[d * 2 + 1];

    float s0 = 0.f, s1 = 0.f;
    for (int k = b0 + lane; k < b1; k += 32) {
        int s = csr[k];
        float2 a = ((const float2*)asrc)[s];
        s0 += __expf(lrelu(a.x + ad0));
        s1 += __expf(lrelu(a.y + ad1));
    }
    s0 = warp_sum(s0); s1 = warp_sum(s1);
    float i0 = 1.f / (s0 + 1e-16f), i1 = 1.f / (s1 + 1e-16f);

    int hh = lane >> 4;
    float iH = hh ? i1 : i0, adH = hh ? ad1 : ad0;
    float2 acc = make_float2(0.f, 0.f);
    const float2* hf2 = (const float2*)hfeat;
#pragma unroll 4
    for (int k = b0; k < b1; k++) {
        int s = csr[k];
        float w = __expf(lrelu(asrc[s * 2 + hh] + adH)) * iH;
        float2 v = hf2[(long long)s * 32 + lane];
        acc.x = fmaf(w, v.x, acc.x);
        acc.y = fmaf(w, v.y, acc.y);
    }
    acc.x += __shfl_xor_sync(FULL, acc.x, 16);
    acc.y += __shfl_xor_sync(FULL, acc.y, 16);
    if (lane < 16) {
        const float2 b = ((const float2*)bias)[lane];
        float ox = fmaxf(acc.x * 0.5f + b.x, 0.f);
        float oy = fmaxf(acc.y * 0.5f + b.y, 0.f);
        int g = batch[d];
        atomicAdd(&sums[g * 32 + 2 * lane], ox);
        atomicAdd(&sums[g * 32 + 2 * lane + 1], oy);
        if (lane == 0) atomicAdd(&gcnt[g], 1.f);
    }
}

// ---------------- heads ----------------
__global__ void k_heads(const float* __restrict__ sums, const float* __restrict__ cnt,
                        const float* __restrict__ cW1, const float* __restrict__ cb1,
                        const float* __restrict__ cW2, const float* __restrict__ cb2,
                        const float* __restrict__ hW1, const float* __restrict__ hb1,
                        const float* __restrict__ hW2, const float* __restrict__ hb2,
                        float* __restrict__ out) {
    int g = threadIdx.x;
    if (g >= GG) return;
    float emb[32];
    float c_ = cnt[g];
    c_ = (c_ > 1.f) ? c_ : 1.f;
    for (int c = 0; c < 32; c++) emb[c] = sums[g * 32 + c] / c_;
    float oh = hb2[0], oc = cb2[0];
    for (int j = 0; j < 16; j++) {
        float sh = hb1[j], sc = cb1[j];
        for (int c = 0; c < 32; c++) {
            sh = fmaf(emb[c], hW1[c * 16 + j], sh);
            sc = fmaf(emb[c], cW1[c * 16 + j], sc);
        }
        sh = fmaxf(sh, 0.f);
        sc = fmaxf(sc, 0.f);
        oh = fmaf(sh, hW2[j], oh);
        oc = fmaf(sc, cW2[j], oc);
    }
    out[g]      = 1.f / (1.f + __expf(-oh));
    out[GG + g] = 1.f / (1.f + __expf(-oc));
}

// ---------------- host ----------------
static inline int cdiv(long long a, int b) { return (int)((a + b - 1) / b); }

extern "C" void kernel_launch(void* const* d_in, const int* in_sizes, int n_in,
                              void* d_out, int out_size) {
    const float* x     = (const float*)d_in[0];
    const int*   ei    = (const int*)  d_in[1];
    const int*   batch = (const int*)  d_in[2];
    const float* W1  = (const float*)d_in[3];
    const float* as1 = (const float*)d_in[4];
    const float* ad1 = (const float*)d_in[5];
    const float* b1  = (const float*)d_in[6];
    const float* W2  = (const float*)d_in[7];
    const float* as2 = (const float*)d_in[8];
    const float* ad2 = (const float*)d_in[9];
    const float* b2  = (const float*)d_in[10];
    const float* cW1 = (const float*)d_in[11];
    const float* cb1 = (const float*)d_in[12];
    const float* cW2 = (const float*)d_in[13];
    const float* cb2 = (const float*)d_in[14];
    const float* hW1 = (const float*)d_in[15];
    const float* hb1 = (const float*)d_in[16];
    const float* hW2 = (const float*)d_in[17];
    const float* hb2 = (const float*)d_in[18];

    const int* src = ei;
    const int* dst = ei + EE;

    float *p_h, *p_h2, *p_asrc, *p_adst, *p_asrc2, *p_adst2, *p_sums, *p_gcnt;
    int *p_cnt, *p_off, *p_cur, *p_csr;
    cudaGetSymbolAddress((void**)&p_h, g_h);
    cudaGetSymbolAddress((void**)&p_h2, g_h2);
    cudaGetSymbolAddress((void**)&p_asrc, g_asrc);
    cudaGetSymbolAddress((void**)&p_adst, g_adst);
    cudaGetSymbolAddress((void**)&p_asrc2, g_asrc2);
    cudaGetSymbolAddress((void**)&p_adst2, g_adst2);
    cudaGetSymbolAddress((void**)&p_cnt, g_cnt);
    cudaGetSymbolAddress((void**)&p_off, g_off);
    cudaGetSymbolAddress((void**)&p_cur, g_cur);
    cudaGetSymbolAddress((void**)&p_csr, g_csr);
    cudaGetSymbolAddress((void**)&p_sums, g_sums);
    cudaGetSymbolAddress((void**)&p_gcnt, g_gcnt);

    const int T = 256;

    // CSR build (dst-sorted)
    cudaMemsetAsync(p_cnt, 0, NN * sizeof(int));
    k_count<<<cdiv(ET, T), T>>>(dst, p_cnt);
    k_scan<<<1, 1024>>>(p_cnt, p_off, p_cur, p_sums, p_gcnt);
    k_build<<<cdiv(ET, T), T>>>(src, dst, p_cur, p_csr);

    // Layer 1 GEMM (register-tiled 4x4) + att coefficients
    // warps = (NN/4)*2 = 10000 -> 320000 threads
    k_gemm1<<<cdiv((long long)(NN / 4) * 2 * 32, T), T>>>(x, W1, as1, ad1, p_h, p_asrc, p_adst);
    // Layer 1 aggregation + fused layer-2 GEMM + att2
    k_agg1<<<cdiv((long long)NN * 32, T), T>>>(p_off, p_csr, p_h, p_asrc, p_adst, b1,
                                               W2, as2, ad2, p_h2, p_asrc2, p_adst2);
    // Layer 2 aggregation + fused mean pool
    k_agg2<<<cdiv((long long)NN * 32, T), T>>>(p_off, p_csr, p_h2, p_asrc2, p_adst2, b2,
                                               batch, p_sums, p_gcnt);
    // Heads
    k_heads<<<1, GG>>>(p_sums, p_gcnt, cW1, cb1, cW2, cb2, hW1, hb1, hW2, hb2,
                       (float*)d_out);
}

// round 5
// speedup vs baseline: 4.4613x; 1.0629x over previous
#include <cuda_runtime.h>
#include <math.h>

#define NN 20000
#define EE 320000
#define ET (EE + NN)
#define GG 64
#define FULL 0xffffffffu
#define GEMM_BLOCKS 625          // 5000 warps / 8 warps-per-block
#define COUNT_BLOCKS ((ET + 255) / 256)

// ---------------- scratch ----------------
__device__ float g_h[NN * 256];
__device__ float g_h2[NN * 64];
__device__ float g_asrc[NN * 4];
__device__ float g_adst[NN * 4];
__device__ float g_asrc2[NN * 2];
__device__ float g_adst2[NN * 2];
__device__ int   g_cnt[NN];
__device__ int   g_off[NN + 1];
__device__ int   g_cur[NN];
__device__ int   g_csr[ET];
__device__ float g_sums[GG * 32];
__device__ float g_gcnt[GG];

__device__ __forceinline__ float lrelu(float v) { return v > 0.f ? v : 0.2f * v; }
__device__ __forceinline__ float warp_sum(float v) {
#pragma unroll
    for (int o = 16; o > 0; o >>= 1) v += __shfl_xor_sync(FULL, v, o);
    return v;
}

// packed f32x2 helpers
#define SPLAT2(out, f) asm("mov.b64 %0, {%1, %1};" : "=l"(out) : "r"(__float_as_uint(f)))
#define FMA2(acc, a, b) asm("fma.rn.f32x2 %0, %1, %2, %0;" : "+l"(acc) : "l"(a), "l"(b))
#define UNPACK2(lo, hi, in) asm("mov.b64 {%0, %1}, %2;" : "=r"(lo), "=r"(hi) : "l"(in))

// ---------------- scan (+ zero pooling buffers) ----------------
__global__ void k_scan(const int* __restrict__ cnt, int* __restrict__ off,
                       int* __restrict__ cur, float* __restrict__ sums,
                       float* __restrict__ gcnt) {
    __shared__ int ssum[1024];
    const int CH = 20;
    int t = threadIdx.x;
    sums[t] = 0.f; sums[t + 1024] = 0.f;
    if (t < GG) gcnt[t] = 0.f;
    int base = t * CH;
    int local[CH];
    int s = 0;
#pragma unroll
    for (int j = 0; j < CH; j++) {
        int v = (base + j < NN) ? cnt[base + j] : 0;
        local[j] = s;
        s += v;
    }
    ssum[t] = s;
    __syncthreads();
    for (int o = 1; o < 1024; o <<= 1) {
        int v = (t >= o) ? ssum[t - o] : 0;
        __syncthreads();
        ssum[t] += v;
        __syncthreads();
    }
    int pre = ssum[t] - s;
#pragma unroll
    for (int j = 0; j < CH; j++) {
        if (base + j < NN) { off[base + j] = pre + local[j]; cur[base + j] = pre + local[j]; }
    }
    if (t == 1023) off[NN] = ssum[1023];
}

__global__ void k_build(const int* __restrict__ src, const int* __restrict__ dst,
                        int* __restrict__ cur, int* __restrict__ csr) {
    int e = blockIdx.x * blockDim.x + threadIdx.x;
    if (e >= ET) return;
    int s = (e < EE) ? src[e] : (e - EE);
    int d = (e < EE) ? dst[e] : (e - EE);
    int pos = atomicAdd(&cur[d], 1);
    csr[pos] = s;
}

// ---------------- GEMM1 (128->256, 8 rows x 4 cols/thread, f32x2) + att1
//                  + fused degree-count (extra blocks) ----------------------
__global__ void k_gemm1_count(const float* __restrict__ A, const float* __restrict__ B,
                              const float* __restrict__ as1, const float* __restrict__ ad1,
                              float* __restrict__ C, float* __restrict__ asrc,
                              float* __restrict__ adst,
                              const int* __restrict__ dst, int* __restrict__ cnt) {
    if (blockIdx.x >= GEMM_BLOCKS) {
        // degree counting branch (independent of GEMM)
        int e = (blockIdx.x - GEMM_BLOCKS) * blockDim.x + threadIdx.x;
        if (e < ET) {
            int d = (e < EE) ? dst[e] : (e - EE);
            atomicAdd(&cnt[d], 1);
        }
        return;
    }

    int gw = blockIdx.x * 8 + (threadIdx.x >> 5);   // 0..4999
    int lane = threadIdx.x & 31;
    int strip = gw >> 1;                            // 0..2499
    int half = gw & 1;
    int cg = half * 32 + lane;                      // col group 0..63
    int row0 = strip * 8;

    const float4* A4 = (const float4*)A;            // [NN][32]
    const ulonglong2* B2 = (const ulonglong2*)B + cg;   // stride 64 per k

    unsigned long long acc[8][2];
#pragma unroll
    for (int r = 0; r < 8; r++) { acc[r][0] = 0ull; acc[r][1] = 0ull; }

#pragma unroll 2
    for (int i = 0; i < 32; i++) {
        ulonglong2 b0 = B2[(4 * i + 0) * 64];
        ulonglong2 b1 = B2[(4 * i + 1) * 64];
        ulonglong2 b2 = B2[(4 * i + 2) * 64];
        ulonglong2 b3 = B2[(4 * i + 3) * 64];
#pragma unroll
        for (int r = 0; r < 8; r++) {
            float4 a = A4[(row0 + r) * 32 + i];
            unsigned long long ax, ay, az, aw;
            SPLAT2(ax, a.x); SPLAT2(ay, a.y); SPLAT2(az, a.z); SPLAT2(aw, a.w);
            FMA2(acc[r][0], ax, b0.x); FMA2(acc[r][1], ax, b0.y);
            FMA2(acc[r][0], ay, b1.x); FMA2(acc[r][1], ay, b1.y);
            FMA2(acc[r][0], az, b2.x); FMA2(acc[r][1], az, b2.y);
            FMA2(acc[r][0], aw, b3.x); FMA2(acc[r][1], aw, b3.y);
        }
    }

    float4 av = ((const float4*)as1)[cg];
    float4 dv = ((const float4*)ad1)[cg];
    float4* C4 = (float4*)C;
    float s[8], dd[8];
#pragma unroll
    for (int r = 0; r < 8; r++) {
        float4 c;
        unsigned int lo, hi;
        UNPACK2(lo, hi, acc[r][0]); c.x = __uint_as_float(lo); c.y = __uint_as_float(hi);
        UNPACK2(lo, hi, acc[r][1]); c.z = __uint_as_float(lo); c.w = __uint_as_float(hi);
        C4[(row0 + r) * 64 + cg] = c;
        s[r]  = c.x * av.x + c.y * av.y + c.z * av.z + c.w * av.w;
        dd[r] = c.x * dv.x + c.y * dv.y + c.z * dv.z + c.w * dv.w;
    }
#pragma unroll
    for (int o = 1; o < 16; o <<= 1) {
#pragma unroll
        for (int r = 0; r < 8; r++) {
            s[r]  += __shfl_xor_sync(FULL, s[r], o);
            dd[r] += __shfl_xor_sync(FULL, dd[r], o);
        }
    }
    if ((lane & 15) == 0) {
        int head = cg >> 4;
#pragma unroll
        for (int r = 0; r < 8; r++) {
            asrc[(row0 + r) * 4 + head] = s[r];
            adst[(row0 + r) * 4 + head] = dd[r];
        }
    }
}

// ---------------- layer 1 aggregation + fused GEMM2 + att2 ----------------
__global__ void k_agg1(const int* __restrict__ off, const int* __restrict__ csr,
                       const float* __restrict__ hfeat, const float* __restrict__ asrc,
                       const float* __restrict__ adst, const float* __restrict__ bias,
                       const float* __restrict__ W2, const float* __restrict__ as2,
                       const float* __restrict__ ad2, float* __restrict__ h2out,
                       float* __restrict__ asrc2, float* __restrict__ adst2) {
    int warp = (blockIdx.x * blockDim.x + threadIdx.x) >> 5;
    if (warp >= NN) return;
    int lane = threadIdx.x & 31;
    int d = warp;
    int b0 = off[d], b1 = off[d + 1];

    float ad0 = adst[d * 4 + 0], ad1 = adst[d * 4 + 1];
    float ad2_ = adst[d * 4 + 2], ad3 = adst[d * 4 + 3];

    float s0 = 0.f, s1 = 0.f, s2 = 0.f, s3 = 0.f;
    for (int k = b0 + lane; k < b1; k += 32) {
        int s = csr[k];
        float4 a = ((const float4*)asrc)[s];
        s0 += __expf(lrelu(a.x + ad0));
        s1 += __expf(lrelu(a.y + ad1));
        s2 += __expf(lrelu(a.z + ad2_));
        s3 += __expf(lrelu(a.w + ad3));
    }
    s0 = warp_sum(s0); s1 = warp_sum(s1); s2 = warp_sum(s2); s3 = warp_sum(s3);
    float i0 = 1.f / (s0 + 1e-16f), i1 = 1.f / (s1 + 1e-16f);
    float i2 = 1.f / (s2 + 1e-16f), i3 = 1.f / (s3 + 1e-16f);

    int hA = lane >> 4;
    float iA  = hA ? i1 : i0,  iB  = hA ? i3 : i2;
    float adA = hA ? ad1 : ad0, adB = hA ? ad3 : ad2_;
    float4 acc0 = make_float4(0.f, 0.f, 0.f, 0.f);
    float4 acc1 = make_float4(0.f, 0.f, 0.f, 0.f);
    const float4* hf4 = (const float4*)hfeat;
    const float4* as4 = (const float4*)asrc;
#pragma unroll 4
    for (int k = b0; k < b1; k++) {
        int s = csr[k];
        float4 a = as4[s];                          // broadcast: 1 wavefront
        float eA = hA ? a.y : a.x;
        float eB = hA ? a.w : a.z;
        float wA = __expf(lrelu(eA + adA)) * iA;
        float wB = __expf(lrelu(eB + adB)) * iB;
        float4 v0 = hf4[(long long)s * 64 + lane];
        float4 v1 = hf4[(long long)s * 64 + 32 + lane];
        acc0.x = fmaf(wA, v0.x, acc0.x); acc0.y = fmaf(wA, v0.y, acc0.y);
        acc0.z = fmaf(wA, v0.z, acc0.z); acc0.w = fmaf(wA, v0.w, acc0.w);
        acc1.x = fmaf(wB, v1.x, acc1.x); acc1.y = fmaf(wB, v1.y, acc1.y);
        acc1.z = fmaf(wB, v1.z, acc1.z); acc1.w = fmaf(wB, v1.w, acc1.w);
    }
    float4 t = make_float4(acc0.x + acc1.x, acc0.y + acc1.y,
                           acc0.z + acc1.z, acc0.w + acc1.w);
    t.x += __shfl_xor_sync(FULL, t.x, 16);
    t.y += __shfl_xor_sync(FULL, t.y, 16);
    t.z += __shfl_xor_sync(FULL, t.z, 16);
    t.w += __shfl_xor_sync(FULL, t.w, 16);

    const float4 bb = ((const float4*)bias)[lane & 15];
    float4 xv;
    xv.x = fmaxf(t.x * 0.25f + bb.x, 0.f);
    xv.y = fmaxf(t.y * 0.25f + bb.y, 0.f);
    xv.z = fmaxf(t.z * 0.25f + bb.z, 0.f);
    xv.w = fmaxf(t.w * 0.25f + bb.w, 0.f);

    const float2* W2f2 = (const float2*)W2;
    float2 h2 = make_float2(0.f, 0.f);
#pragma unroll
    for (int g = 0; g < 16; g++) {
        float vx = __shfl_sync(FULL, xv.x, g);
        float vy = __shfl_sync(FULL, xv.y, g);
        float vz = __shfl_sync(FULL, xv.z, g);
        float vw = __shfl_sync(FULL, xv.w, g);
        float2 w0 = W2f2[(g * 4 + 0) * 32 + lane];
        float2 w1 = W2f2[(g * 4 + 1) * 32 + lane];
        float2 w2 = W2f2[(g * 4 + 2) * 32 + lane];
        float2 w3 = W2f2[(g * 4 + 3) * 32 + lane];
        h2.x = fmaf(vx, w0.x, h2.x); h2.y = fmaf(vx, w0.y, h2.y);
        h2.x = fmaf(vy, w1.x, h2.x); h2.y = fmaf(vy, w1.y, h2.y);
        h2.x = fmaf(vz, w2.x, h2.x); h2.y = fmaf(vz, w2.y, h2.y);
        h2.x = fmaf(vw, w3.x, h2.x); h2.y = fmaf(vw, w3.y, h2.y);
    }
    ((float2*)h2out)[d * 32 + lane] = h2;

    float2 a2 = ((const float2*)as2)[lane];
    float2 d2 = ((const float2*)ad2)[lane];
    float ps = h2.x * a2.x + h2.y * a2.y;
    float pd = h2.x * d2.x + h2.y * d2.y;
#pragma unroll
    for (int o = 1; o < 16; o <<= 1) {
        ps += __shfl_xor_sync(FULL, ps, o);
        pd += __shfl_xor_sync(FULL, pd, o);
    }
    if ((lane & 15) == 0) {
        asrc2[d * 2 + hA] = ps;
        adst2[d * 2 + hA] = pd;
    }
}

// ---------------- layer 2 aggregation + fused global mean pool -------------
__global__ void k_agg2(const int* __restrict__ off, const int* __restrict__ csr,
                       const float* __restrict__ hfeat, const float* __restrict__ asrc,
                       const float* __restrict__ adst, const float* __restrict__ bias,
                       const int* __restrict__ batch, float* __restrict__ sums,
                       float* __restrict__ gcnt) {
    int warp = (blockIdx.x * blockDim.x + threadIdx.x) >> 5;
    if (warp >= NN) return;
    int lane = threadIdx.x & 31;
    int d = warp;
    int b0 = off[d], b1 = off[d + 1];

    float ad0 = adst[d * 2 + 0], ad1 = adst[d * 2 + 1];

    float s0 = 0.f, s1 = 0.f;
    for (int k = b0 + lane; k < b1; k += 32) {
        int s = csr[k];
        float2 a = ((const float2*)asrc)[s];
        s0 += __expf(lrelu(a.x + ad0));
        s1 += __expf(lrelu(a.y + ad1));
    }
    s0 = warp_sum(s0); s1 = warp_sum(s1);
    float i0 = 1.f / (s0 + 1e-16f), i1 = 1.f / (s1 + 1e-16f);

    int hh = lane >> 4;
    float iH = hh ? i1 : i0, adH = hh ? ad1 : ad0;
    float2 acc = make_float2(0.f, 0.f);
    const float2* hf2 = (const float2*)hfeat;
    const float2* as2p = (const float2*)asrc;
#pragma unroll 4
    for (int k = b0; k < b1; k++) {
        int s = csr[k];
        float2 a = as2p[s];                          // broadcast
        float e = hh ? a.y : a.x;
        float w = __expf(lrelu(e + adH)) * iH;
        float2 v = hf2[(long long)s * 32 + lane];
        acc.x = fmaf(w, v.x, acc.x);
        acc.y = fmaf(w, v.y, acc.y);
    }
    acc.x += __shfl_xor_sync(FULL, acc.x, 16);
    acc.y += __shfl_xor_sync(FULL, acc.y, 16);
    if (lane < 16) {
        const float2 b = ((const float2*)bias)[lane];
        float ox = fmaxf(acc.x * 0.5f + b.x, 0.f);
        float oy = fmaxf(acc.y * 0.5f + b.y, 0.f);
        int g = batch[d];
        atomicAdd(&sums[g * 32 + 2 * lane], ox);
        atomicAdd(&sums[g * 32 + 2 * lane + 1], oy);
        if (lane == 0) atomicAdd(&gcnt[g], 1.f);
    }
}

// ---------------- heads ----------------
__global__ void k_heads(const float* __restrict__ sums, const float* __restrict__ cnt,
                        const float* __restrict__ cW1, const float* __restrict__ cb1,
                        const float* __restrict__ cW2, const float* __restrict__ cb2,
                        const float* __restrict__ hW1, const float* __restrict__ hb1,
                        const float* __restrict__ hW2, const float* __restrict__ hb2,
                        float* __restrict__ out) {
    int g = threadIdx.x;
    if (g >= GG) return;
    float emb[32];
    float c_ = cnt[g];
    c_ = (c_ > 1.f) ? c_ : 1.f;
    for (int c = 0; c < 32; c++) emb[c] = sums[g * 32 + c] / c_;
    float oh = hb2[0], oc = cb2[0];
    for (int j = 0; j < 16; j++) {
        float sh = hb1[j], sc = cb1[j];
        for (int c = 0; c < 32; c++) {
            sh = fmaf(emb[c], hW1[c * 16 + j], sh);
            sc = fmaf(emb[c], cW1[c * 16 + j], sc);
        }
        sh = fmaxf(sh, 0.f);
        sc = fmaxf(sc, 0.f);
        oh = fmaf(sh, hW2[j], oh);
        oc = fmaf(sc, cW2[j], oc);
    }
    out[g]      = 1.f / (1.f + __expf(-oh));
    out[GG + g] = 1.f / (1.f + __expf(-oc));
}

// ---------------- host ----------------
static inline int cdiv(long long a, int b) { return (int)((a + b - 1) / b); }

extern "C" void kernel_launch(void* const* d_in, const int* in_sizes, int n_in,
                              void* d_out, int out_size) {
    const float* x     = (const float*)d_in[0];
    const int*   ei    = (const int*)  d_in[1];
    const int*   batch = (const int*)  d_in[2];
    const float* W1  = (const float*)d_in[3];
    const float* as1 = (const float*)d_in[4];
    const float* ad1 = (const float*)d_in[5];
    const float* b1  = (const float*)d_in[6];
    const float* W2  = (const float*)d_in[7];
    const float* as2 = (const float*)d_in[8];
    const float* ad2 = (const float*)d_in[9];
    const float* b2  = (const float*)d_in[10];
    const float* cW1 = (const float*)d_in[11];
    const float* cb1 = (const float*)d_in[12];
    const float* cW2 = (const float*)d_in[13];
    const float* cb2 = (const float*)d_in[14];
    const float* hW1 = (const float*)d_in[15];
    const float* hb1 = (const float*)d_in[16];
    const float* hW2 = (const float*)d_in[17];
    const float* hb2 = (const float*)d_in[18];

    const int* src = ei;
    const int* dst = ei + EE;

    float *p_h, *p_h2, *p_asrc, *p_adst, *p_asrc2, *p_adst2, *p_sums, *p_gcnt;
    int *p_cnt, *p_off, *p_cur, *p_csr;
    cudaGetSymbolAddress((void**)&p_h, g_h);
    cudaGetSymbolAddress((void**)&p_h2, g_h2);
    cudaGetSymbolAddress((void**)&p_asrc, g_asrc);
    cudaGetSymbolAddress((void**)&p_adst, g_adst);
    cudaGetSymbolAddress((void**)&p_asrc2, g_asrc2);
    cudaGetSymbolAddress((void**)&p_adst2, g_adst2);
    cudaGetSymbolAddress((void**)&p_cnt, g_cnt);
    cudaGetSymbolAddress((void**)&p_off, g_off);
    cudaGetSymbolAddress((void**)&p_cur, g_cur);
    cudaGetSymbolAddress((void**)&p_csr, g_csr);
    cudaGetSymbolAddress((void**)&p_sums, g_sums);
    cudaGetSymbolAddress((void**)&p_gcnt, g_gcnt);

    const int T = 256;

    cudaMemsetAsync(p_cnt, 0, NN * sizeof(int));
    // GEMM1 (+att1) and degree-count fused in one launch (independent blocks)
    k_gemm1_count<<<GEMM_BLOCKS + COUNT_BLOCKS, T>>>(x, W1, as1, ad1, p_h,
                                                     p_asrc, p_adst, dst, p_cnt);
    k_scan<<<1, 1024>>>(p_cnt, p_off, p_cur, p_sums, p_gcnt);
    k_build<<<cdiv(ET, T), T>>>(src, dst, p_cur, p_csr);

    // Layer 1 aggregation + fused layer-2 GEMM + att2
    k_agg1<<<cdiv((long long)NN * 32, T), T>>>(p_off, p_csr, p_h, p_asrc, p_adst, b1,
                                               W2, as2, ad2, p_h2, p_asrc2, p_adst2);
    // Layer 2 aggregation + fused mean pool
    k_agg2<<<cdiv((long long)NN * 32, T), T>>>(p_off, p_csr, p_h2, p_asrc2, p_adst2, b2,
                                               batch, p_sums, p_gcnt);
    // Heads
    k_heads<<<1, GG>>>(p_sums, p_gcnt, cW1, cb1, cW2, cb2, hW1, hb1, hW2, hb2,
                       (float*)d_out);
}

// round 6
// speedup vs baseline: 4.5140x; 1.0118x over previous
#include <cuda_runtime.h>
#include <cuda_fp16.h>
#include <math.h>

#define NN 20000
#define EE 320000
#define ET (EE + NN)
#define GG 64
#define FULL 0xffffffffu
#define GEMM_BLOCKS 625                   // 5000 warps / 8 per block
#define COUNT_BLOCKS ((EE / 4 + 255) / 256)

// ---------------- scratch ----------------
__device__ __half g_h[NN * 256];      // layer-1 features, fp16
__device__ __half g_h2[NN * 64];      // layer-2 features, fp16
__device__ float g_asrc[NN * 4];
__device__ float g_adst[NN * 4];
__device__ float g_asrc2[NN * 2];
__device__ float g_adst2[NN * 2];
__device__ int   g_cnt[NN];
__device__ int   g_off[NN + 1];
__device__ int   g_cur[NN];
__device__ int   g_csr[ET];
__device__ float g_sums[GG * 32];
__device__ float g_gcnt[GG];

__device__ __forceinline__ float lrelu(float v) { return v > 0.f ? v : 0.2f * v; }
__device__ __forceinline__ float warp_sum(float v) {
#pragma unroll
    for (int o = 16; o > 0; o >>= 1) v += __shfl_xor_sync(FULL, v, o);
    return v;
}

// packed f32x2 helpers
#define SPLAT2(out, f) asm("mov.b64 %0, {%1, %1};" : "=l"(out) : "r"(__float_as_uint(f)))
#define FMA2(acc, a, b) asm("fma.rn.f32x2 %0, %1, %2, %0;" : "+l"(acc) : "l"(a), "l"(b))
#define UNPACK2(lo, hi, in) asm("mov.b64 {%0, %1}, %2;" : "=r"(lo), "=r"(hi) : "l"(in))

// ---------------- scan (+1 self-loop per node; zero pooling buffers) -------
__global__ void k_scan(const int* __restrict__ cnt, int* __restrict__ off,
                       int* __restrict__ cur, float* __restrict__ sums,
                       float* __restrict__ gcnt) {
    __shared__ int ssum[1024];
    const int CH = 20;
    int t = threadIdx.x;
    sums[t] = 0.f; sums[t + 1024] = 0.f;
    if (t < GG) gcnt[t] = 0.f;
    int base = t * CH;
    int local[CH];
    int s = 0;
#pragma unroll
    for (int j = 0; j < CH; j++) {
        int v = (base + j < NN) ? (cnt[base + j] + 1) : 0;   // +1 = self loop
        local[j] = s;
        s += v;
    }
    ssum[t] = s;
    __syncthreads();
    for (int o = 1; o < 1024; o <<= 1) {
        int v = (t >= o) ? ssum[t - o] : 0;
        __syncthreads();
        ssum[t] += v;
        __syncthreads();
    }
    int pre = ssum[t] - s;
#pragma unroll
    for (int j = 0; j < CH; j++) {
        if (base + j < NN) { off[base + j] = pre + local[j]; cur[base + j] = pre + local[j]; }
    }
    if (t == 1023) off[NN] = ssum[1023];
}

// ---------------- CSR fill: 4 edges per thread + self-loop tail ------------
__global__ void k_build(const int* __restrict__ src, const int* __restrict__ dst,
                        int* __restrict__ cur, int* __restrict__ csr) {
    int t = blockIdx.x * blockDim.x + threadIdx.x;
    if (t < EE / 4) {
        int4 s4 = ((const int4*)src)[t];
        int4 d4 = ((const int4*)dst)[t];
        csr[atomicAdd(&cur[d4.x], 1)] = s4.x;
        csr[atomicAdd(&cur[d4.y], 1)] = s4.y;
        csr[atomicAdd(&cur[d4.z], 1)] = s4.z;
        csr[atomicAdd(&cur[d4.w], 1)] = s4.w;
    } else {
        int n = t - EE / 4;
        if (n < NN) csr[atomicAdd(&cur[n], 1)] = n;
    }
}

// ---------------- GEMM1 (fp32 in, fp16 out) + att1 + fused degree count ----
__global__ void k_gemm1_count(const float* __restrict__ A, const float* __restrict__ B,
                              const float* __restrict__ as1, const float* __restrict__ ad1,
                              __half* __restrict__ C, float* __restrict__ asrc,
                              float* __restrict__ adst,
                              const int* __restrict__ dst, int* __restrict__ cnt) {
    if (blockIdx.x >= GEMM_BLOCKS) {
        int t = (blockIdx.x - GEMM_BLOCKS) * blockDim.x + threadIdx.x;
        if (t < EE / 4) {
            int4 d4 = ((const int4*)dst)[t];
            atomicAdd(&cnt[d4.x], 1);
            atomicAdd(&cnt[d4.y], 1);
            atomicAdd(&cnt[d4.z], 1);
            atomicAdd(&cnt[d4.w], 1);
        }
        return;
    }

    int gw = blockIdx.x * 8 + (threadIdx.x >> 5);
    int lane = threadIdx.x & 31;
    int strip = gw >> 1;
    int half_ = gw & 1;
    int cg = half_ * 32 + lane;               // col group 0..63 (4 cols)
    int row0 = strip * 8;

    const float4* A4 = (const float4*)A;
    const ulonglong2* B2 = (const ulonglong2*)B + cg;

    unsigned long long acc[8][2];
#pragma unroll
    for (int r = 0; r < 8; r++) { acc[r][0] = 0ull; acc[r][1] = 0ull; }

#pragma unroll 2
    for (int i = 0; i < 32; i++) {
        ulonglong2 b0 = B2[(4 * i + 0) * 64];
        ulonglong2 b1 = B2[(4 * i + 1) * 64];
        ulonglong2 b2 = B2[(4 * i + 2) * 64];
        ulonglong2 b3 = B2[(4 * i + 3) * 64];
#pragma unroll
        for (int r = 0; r < 8; r++) {
            float4 a = A4[(row0 + r) * 32 + i];
            unsigned long long ax, ay, az, aw;
            SPLAT2(ax, a.x); SPLAT2(ay, a.y); SPLAT2(az, a.z); SPLAT2(aw, a.w);
            FMA2(acc[r][0], ax, b0.x); FMA2(acc[r][1], ax, b0.y);
            FMA2(acc[r][0], ay, b1.x); FMA2(acc[r][1], ay, b1.y);
            FMA2(acc[r][0], az, b2.x); FMA2(acc[r][1], az, b2.y);
            FMA2(acc[r][0], aw, b3.x); FMA2(acc[r][1], aw, b3.y);
        }
    }

    float4 av = ((const float4*)as1)[cg];
    float4 dv = ((const float4*)ad1)[cg];
    uint2* C2 = (uint2*)C;                    // 8B = 4 halfs per lane per row
    float s[8], dd[8];
#pragma unroll
    for (int r = 0; r < 8; r++) {
        float4 c;
        unsigned int lo, hi;
        UNPACK2(lo, hi, acc[r][0]); c.x = __uint_as_float(lo); c.y = __uint_as_float(hi);
        UNPACK2(lo, hi, acc[r][1]); c.z = __uint_as_float(lo); c.w = __uint_as_float(hi);
        half2 p0 = __floats2half2_rn(c.x, c.y);
        half2 p1 = __floats2half2_rn(c.z, c.w);
        uint2 pk;
        pk.x = *(unsigned int*)&p0;
        pk.y = *(unsigned int*)&p1;
        C2[(row0 + r) * 64 + cg] = pk;
        s[r]  = c.x * av.x + c.y * av.y + c.z * av.z + c.w * av.w;
        dd[r] = c.x * dv.x + c.y * dv.y + c.z * dv.z + c.w * dv.w;
    }
#pragma unroll
    for (int o = 1; o < 16; o <<= 1) {
#pragma unroll
        for (int r = 0; r < 8; r++) {
            s[r]  += __shfl_xor_sync(FULL, s[r], o);
            dd[r] += __shfl_xor_sync(FULL, dd[r], o);
        }
    }
    if ((lane & 15) == 0) {
        int head = cg >> 4;
#pragma unroll
        for (int r = 0; r < 8; r++) {
            asrc[(row0 + r) * 4 + head] = s[r];
            adst[(row0 + r) * 4 + head] = dd[r];
        }
    }
}

// ---------------- layer 1 aggregation (fp16 gather) + GEMM2 + att2 ---------
__global__ void k_agg1(const int* __restrict__ off, const int* __restrict__ csr,
                       const __half* __restrict__ hfeat, const float* __restrict__ asrc,
                       const float* __restrict__ adst, const float* __restrict__ bias,
                       const float* __restrict__ W2, const float* __restrict__ as2,
                       const float* __restrict__ ad2, __half* __restrict__ h2out,
                       float* __restrict__ asrc2, float* __restrict__ adst2) {
    int warp = (blockIdx.x * blockDim.x + threadIdx.x) >> 5;
    if (warp >= NN) return;
    int lane = threadIdx.x & 31;
    int d = warp;
    int b0 = off[d], b1 = off[d + 1];

    float ad0 = adst[d * 4 + 0], ad1 = adst[d * 4 + 1];
    float ad2_ = adst[d * 4 + 2], ad3 = adst[d * 4 + 3];

    // denominators
    float s0 = 0.f, s1 = 0.f, s2 = 0.f, s3 = 0.f;
    for (int k = b0 + lane; k < b1; k += 32) {
        int s = csr[k];
        float4 a = ((const float4*)asrc)[s];
        s0 += __expf(lrelu(a.x + ad0));
        s1 += __expf(lrelu(a.y + ad1));
        s2 += __expf(lrelu(a.z + ad2_));
        s3 += __expf(lrelu(a.w + ad3));
    }
    s0 = warp_sum(s0); s1 = warp_sum(s1); s2 = warp_sum(s2); s3 = warp_sum(s3);
    float i0 = 1.f / (s0 + 1e-16f), i1 = 1.f / (s1 + 1e-16f);
    float i2 = 1.f / (s2 + 1e-16f), i3 = 1.f / (s3 + 1e-16f);

    // lane owns channels 8*lane..8*lane+7; head = lane>>3
    int hh = lane >> 3;
    float adH = (hh == 0) ? ad0 : (hh == 1) ? ad1 : (hh == 2) ? ad2_ : ad3;
    float iH  = (hh == 0) ? i0  : (hh == 1) ? i1  : (hh == 2) ? i2  : i3;

    float acc[8];
#pragma unroll
    for (int j = 0; j < 8; j++) acc[j] = 0.f;

    const uint4* hf = (const uint4*)hfeat;    // 32 uint4 per row
    const float4* as4 = (const float4*)asrc;
#pragma unroll 4
    for (int k = b0; k < b1; k++) {
        int s = csr[k];
        float4 a = as4[s];                    // broadcast
        float ev = (hh == 0) ? a.x : (hh == 1) ? a.y : (hh == 2) ? a.z : a.w;
        float w = __expf(lrelu(ev + adH)) * iH;
        uint4 v = hf[s * 32 + lane];          // 8 halfs = channels 8L..8L+7
        float2 p0 = __half22float2(*(half2*)&v.x);
        float2 p1 = __half22float2(*(half2*)&v.y);
        float2 p2 = __half22float2(*(half2*)&v.z);
        float2 p3 = __half22float2(*(half2*)&v.w);
        acc[0] = fmaf(w, p0.x, acc[0]); acc[1] = fmaf(w, p0.y, acc[1]);
        acc[2] = fmaf(w, p1.x, acc[2]); acc[3] = fmaf(w, p1.y, acc[3]);
        acc[4] = fmaf(w, p2.x, acc[4]); acc[5] = fmaf(w, p2.y, acc[5]);
        acc[6] = fmaf(w, p3.x, acc[6]); acc[7] = fmaf(w, p3.y, acc[7]);
    }

    // head mean: channel c lives on lanes (c>>3)&7, +8, +16, +24
#pragma unroll
    for (int j = 0; j < 8; j++) {
        acc[j] += __shfl_xor_sync(FULL, acc[j], 8);
        acc[j] += __shfl_xor_sync(FULL, acc[j], 16);
    }
    // all lanes: acc[j] = head-sum for channel 8*(lane&7)+j
    int cq = lane & 7;
    float4 bb0 = ((const float4*)bias)[cq * 2];
    float4 bb1 = ((const float4*)bias)[cq * 2 + 1];
    float xv[8];
    xv[0] = fmaxf(acc[0] * 0.25f + bb0.x, 0.f);
    xv[1] = fmaxf(acc[1] * 0.25f + bb0.y, 0.f);
    xv[2] = fmaxf(acc[2] * 0.25f + bb0.z, 0.f);
    xv[3] = fmaxf(acc[3] * 0.25f + bb0.w, 0.f);
    xv[4] = fmaxf(acc[4] * 0.25f + bb1.x, 0.f);
    xv[5] = fmaxf(acc[5] * 0.25f + bb1.y, 0.f);
    xv[6] = fmaxf(acc[6] * 0.25f + bb1.z, 0.f);
    xv[7] = fmaxf(acc[7] * 0.25f + bb1.w, 0.f);

    // fused GEMM2: x1[8g+j] lives on lane g (j-th reg); lane computes cols 2L,2L+1
    const float2* W2f2 = (const float2*)W2;
    float2 h2 = make_float2(0.f, 0.f);
#pragma unroll
    for (int g = 0; g < 8; g++) {
#pragma unroll
        for (int j = 0; j < 8; j++) {
            float v = __shfl_sync(FULL, xv[j], g);
            float2 w = W2f2[(8 * g + j) * 32 + lane];
            h2.x = fmaf(v, w.x, h2.x);
            h2.y = fmaf(v, w.y, h2.y);
        }
    }
    half2 h2h = __floats2half2_rn(h2.x, h2.y);
    ((half2*)h2out)[d * 32 + lane] = h2h;

    // att2: head = lane>>4, channels 2*(lane&15)+{0,1}
    float2 a2 = ((const float2*)as2)[lane];
    float2 d2 = ((const float2*)ad2)[lane];
    float ps = h2.x * a2.x + h2.y * a2.y;
    float pd = h2.x * d2.x + h2.y * d2.y;
#pragma unroll
    for (int o = 1; o < 16; o <<= 1) {
        ps += __shfl_xor_sync(FULL, ps, o);
        pd += __shfl_xor_sync(FULL, pd, o);
    }
    if ((lane & 15) == 0) {
        asrc2[d * 2 + (lane >> 4)] = ps;
        adst2[d * 2 + (lane >> 4)] = pd;
    }
}

// ---------------- layer 2 aggregation (fp16 gather) + mean pool ------------
__global__ void k_agg2(const int* __restrict__ off, const int* __restrict__ csr,
                       const __half* __restrict__ hfeat, const float* __restrict__ asrc,
                       const float* __restrict__ adst, const float* __restrict__ bias,
                       const int* __restrict__ batch, float* __restrict__ sums,
                       float* __restrict__ gcnt) {
    int warp = (blockIdx.x * blockDim.x + threadIdx.x) >> 5;
    if (warp >= NN) return;
    int lane = threadIdx.x & 31;
    int d = warp;
    int b0 = off[d], b1 = off[d + 1];

    float ad0 = adst[d * 2 + 0], ad1 = adst[d * 2 + 1];

    float s0 = 0.f, s1 = 0.f;
    for (int k = b0 + lane; k < b1; k += 32) {
        int s = csr[k];
        float2 a = ((const float2*)asrc)[s];
        s0 += __expf(lrelu(a.x + ad0));
        s1 += __expf(lrelu(a.y + ad1));
    }
    s0 = warp_sum(s0); s1 = warp_sum(s1);
    float i0 = 1.f / (s0 + 1e-16f), i1 = 1.f / (s1 + 1e-16f);

    int hh = lane >> 4;
    float iH = hh ? i1 : i0, adH = hh ? ad1 : ad0;
    float2 acc = make_float2(0.f, 0.f);
    const half2* hf = (const half2*)hfeat;    // 32 half2 per row
    const float2* as2p = (const float2*)asrc;
#pragma unroll 4
    for (int k = b0; k < b1; k++) {
        int s = csr[k];
        float2 a = as2p[s];
        float e = hh ? a.y : a.x;
        float w = __expf(lrelu(e + adH)) * iH;
        float2 v = __half22float2(hf[s * 32 + lane]);
        acc.x = fmaf(w, v.x, acc.x);
        acc.y = fmaf(w, v.y, acc.y);
    }
    acc.x += __shfl_xor_sync(FULL, acc.x, 16);
    acc.y += __shfl_xor_sync(FULL, acc.y, 16);
    if (lane < 16) {
        const float2 b = ((const float2*)bias)[lane];
        float ox = fmaxf(acc.x * 0.5f + b.x, 0.f);
        float oy = fmaxf(acc.y * 0.5f + b.y, 0.f);
        int g = batch[d];
        atomicAdd(&sums[g * 32 + 2 * lane], ox);
        atomicAdd(&sums[g * 32 + 2 * lane + 1], oy);
        if (lane == 0) atomicAdd(&gcnt[g], 1.f);
    }
}

// ---------------- heads ----------------
__global__ void k_heads(const float* __restrict__ sums, const float* __restrict__ cnt,
                        const float* __restrict__ cW1, const float* __restrict__ cb1,
                        const float* __restrict__ cW2, const float* __restrict__ cb2,
                        const float* __restrict__ hW1, const float* __restrict__ hb1,
                        const float* __restrict__ hW2, const float* __restrict__ hb2,
                        float* __restrict__ out) {
    int g = threadIdx.x;
    if (g >= GG) return;
    float emb[32];
    float c_ = cnt[g];
    c_ = (c_ > 1.f) ? c_ : 1.f;
    for (int c = 0; c < 32; c++) emb[c] = sums[g * 32 + c] / c_;
    float oh = hb2[0], oc = cb2[0];
    for (int j = 0; j < 16; j++) {
        float sh = hb1[j], sc = cb1[j];
        for (int c = 0; c < 32; c++) {
            sh = fmaf(emb[c], hW1[c * 16 + j], sh);
            sc = fmaf(emb[c], cW1[c * 16 + j], sc);
        }
        sh = fmaxf(sh, 0.f);
        sc = fmaxf(sc, 0.f);
        oh = fmaf(sh, hW2[j], oh);
        oc = fmaf(sc, cW2[j], oc);
    }
    out[g]      = 1.f / (1.f + __expf(-oh));
    out[GG + g] = 1.f / (1.f + __expf(-oc));
}

// ---------------- host ----------------
static inline int cdiv(long long a, int b) { return (int)((a + b - 1) / b); }

extern "C" void kernel_launch(void* const* d_in, const int* in_sizes, int n_in,
                              void* d_out, int out_size) {
    const float* x     = (const float*)d_in[0];
    const int*   ei    = (const int*)  d_in[1];
    const int*   batch = (const int*)  d_in[2];
    const float* W1  = (const float*)d_in[3];
    const float* as1 = (const float*)d_in[4];
    const float* ad1 = (const float*)d_in[5];
    const float* b1  = (const float*)d_in[6];
    const float* W2  = (const float*)d_in[7];
    const float* as2 = (const float*)d_in[8];
    const float* ad2 = (const float*)d_in[9];
    const float* b2  = (const float*)d_in[10];
    const float* cW1 = (const float*)d_in[11];
    const float* cb1 = (const float*)d_in[12];
    const float* cW2 = (const float*)d_in[13];
    const float* cb2 = (const float*)d_in[14];
    const float* hW1 = (const float*)d_in[15];
    const float* hb1 = (const float*)d_in[16];
    const float* hW2 = (const float*)d_in[17];
    const float* hb2 = (const float*)d_in[18];

    const int* src = ei;
    const int* dst = ei + EE;

    __half *p_h, *p_h2;
    float *p_asrc, *p_adst, *p_asrc2, *p_adst2, *p_sums, *p_gcnt;
    int *p_cnt, *p_off, *p_cur, *p_csr;
    cudaGetSymbolAddress((void**)&p_h, g_h);
    cudaGetSymbolAddress((void**)&p_h2, g_h2);
    cudaGetSymbolAddress((void**)&p_asrc, g_asrc);
    cudaGetSymbolAddress((void**)&p_adst, g_adst);
    cudaGetSymbolAddress((void**)&p_asrc2, g_asrc2);
    cudaGetSymbolAddress((void**)&p_adst2, g_adst2);
    cudaGetSymbolAddress((void**)&p_cnt, g_cnt);
    cudaGetSymbolAddress((void**)&p_off, g_off);
    cudaGetSymbolAddress((void**)&p_cur, g_cur);
    cudaGetSymbolAddress((void**)&p_csr, g_csr);
    cudaGetSymbolAddress((void**)&p_sums, g_sums);
    cudaGetSymbolAddress((void**)&p_gcnt, g_gcnt);

    const int T = 256;

    cudaMemsetAsync(p_cnt, 0, NN * sizeof(int));
    // GEMM1 (+att1) and degree count fused (independent block ranges)
    k_gemm1_count<<<GEMM_BLOCKS + COUNT_BLOCKS, T>>>(x, W1, as1, ad1, p_h,
                                                     p_asrc, p_adst, dst, p_cnt);
    k_scan<<<1, 1024>>>(p_cnt, p_off, p_cur, p_sums, p_gcnt);
    k_build<<<cdiv(EE / 4 + NN, T), T>>>(src, dst, p_cur, p_csr);

    k_agg1<<<cdiv((long long)NN * 32, T), T>>>(p_off, p_csr, p_h, p_asrc, p_adst, b1,
                                               W2, as2, ad2, p_h2, p_asrc2, p_adst2);
    k_agg2<<<cdiv((long long)NN * 32, T), T>>>(p_off, p_csr, p_h2, p_asrc2, p_adst2, b2,
                                               batch, p_sums, p_gcnt);
    k_heads<<<1, GG>>>(p_sums, p_gcnt, cW1, cb1, cW2, cb2, hW1, hb1, hW2, hb2,
                       (float*)d_out);
}

// round 7
// speedup vs baseline: 4.7754x; 1.0579x over previous
#include <cuda_runtime.h>
#include <cuda_fp16.h>
#include <math.h>

#define NN 20000
#define EE 320000
#define ET (EE + NN)
#define GG 64
#define FULL 0xffffffffu
#define GEMM_BLOCKS 625                   // 5000 warps / 8 per block
#define COUNT_BLOCKS ((EE / 4 + 255) / 256)

// ---------------- scratch ----------------
__device__ __half g_h[NN * 256];
__device__ __half g_h2[NN * 64];
__device__ float g_asrc[NN * 4];
__device__ float g_adst[NN * 4];
__device__ float g_asrc2[NN * 2];
__device__ float g_adst2[NN * 2];
__device__ int   g_cnt[NN];
__device__ int   g_off[NN + 1];
__device__ int   g_cur[NN];
__device__ int   g_csr[ET];
__device__ float g_sums[GG * 32];
__device__ float g_gcnt[GG];

__device__ __forceinline__ float lrelu(float v) { return v > 0.f ? v : 0.2f * v; }
__device__ __forceinline__ float warp_sum(float v) {
#pragma unroll
    for (int o = 16; o > 0; o >>= 1) v += __shfl_xor_sync(FULL, v, o);
    return v;
}

// packed f32x2 helpers
#define SPLAT2(out, f) asm("mov.b64 %0, {%1, %1};" : "=l"(out) : "r"(__float_as_uint(f)))
#define FMA2(acc, a, b) asm("fma.rn.f32x2 %0, %1, %2, %0;" : "+l"(acc) : "l"(a), "l"(b))
#define UNPACK2(lo, hi, in) asm("mov.b64 {%0, %1}, %2;" : "=r"(lo), "=r"(hi) : "l"(in))

// ---------------- scan (+1 self-loop; zero pooling buffers) ----------------
__global__ void k_scan(const int* __restrict__ cnt, int* __restrict__ off,
                       int* __restrict__ cur, float* __restrict__ sums,
                       float* __restrict__ gcnt) {
    __shared__ int ssum[1024];
    const int CH = 20;
    int t = threadIdx.x;
    sums[t] = 0.f; sums[t + 1024] = 0.f;
    if (t < GG) gcnt[t] = 0.f;
    int base = t * CH;
    int local[CH];
    int s = 0;
#pragma unroll
    for (int j = 0; j < CH; j++) {
        int v = (base + j < NN) ? (cnt[base + j] + 1) : 0;
        local[j] = s;
        s += v;
    }
    ssum[t] = s;
    __syncthreads();
    for (int o = 1; o < 1024; o <<= 1) {
        int v = (t >= o) ? ssum[t - o] : 0;
        __syncthreads();
        ssum[t] += v;
        __syncthreads();
    }
    int pre = ssum[t] - s;
#pragma unroll
    for (int j = 0; j < CH; j++) {
        if (base + j < NN) { off[base + j] = pre + local[j]; cur[base + j] = pre + local[j]; }
    }
    if (t == 1023) off[NN] = ssum[1023];
}

// ---------------- CSR fill ----------------
__global__ void k_build(const int* __restrict__ src, const int* __restrict__ dst,
                        int* __restrict__ cur, int* __restrict__ csr) {
    int t = blockIdx.x * blockDim.x + threadIdx.x;
    if (t < EE / 4) {
        int4 s4 = ((const int4*)src)[t];
        int4 d4 = ((const int4*)dst)[t];
        csr[atomicAdd(&cur[d4.x], 1)] = s4.x;
        csr[atomicAdd(&cur[d4.y], 1)] = s4.y;
        csr[atomicAdd(&cur[d4.z], 1)] = s4.z;
        csr[atomicAdd(&cur[d4.w], 1)] = s4.w;
    } else {
        int n = t - EE / 4;
        if (n < NN) csr[atomicAdd(&cur[n], 1)] = n;
    }
}

// ---------------- GEMM1 (fp32 in, fp16 out) + att1 + fused degree count ----
__global__ void k_gemm1_count(const float* __restrict__ A, const float* __restrict__ B,
                              const float* __restrict__ as1, const float* __restrict__ ad1,
                              __half* __restrict__ C, float* __restrict__ asrc,
                              float* __restrict__ adst,
                              const int* __restrict__ dst, int* __restrict__ cnt) {
    if (blockIdx.x >= GEMM_BLOCKS) {
        int t = (blockIdx.x - GEMM_BLOCKS) * blockDim.x + threadIdx.x;
        if (t < EE / 4) {
            int4 d4 = ((const int4*)dst)[t];
            atomicAdd(&cnt[d4.x], 1);
            atomicAdd(&cnt[d4.y], 1);
            atomicAdd(&cnt[d4.z], 1);
            atomicAdd(&cnt[d4.w], 1);
        }
        return;
    }

    int gw = blockIdx.x * 8 + (threadIdx.x >> 5);
    int lane = threadIdx.x & 31;
    int strip = gw >> 1;
    int half_ = gw & 1;
    int cg = half_ * 32 + lane;
    int row0 = strip * 8;

    const float4* A4 = (const float4*)A;
    const ulonglong2* B2 = (const ulonglong2*)B + cg;

    unsigned long long acc[8][2];
#pragma unroll
    for (int r = 0; r < 8; r++) { acc[r][0] = 0ull; acc[r][1] = 0ull; }

#pragma unroll 2
    for (int i = 0; i < 32; i++) {
        ulonglong2 b0 = B2[(4 * i + 0) * 64];
        ulonglong2 b1 = B2[(4 * i + 1) * 64];
        ulonglong2 b2 = B2[(4 * i + 2) * 64];
        ulonglong2 b3 = B2[(4 * i + 3) * 64];
#pragma unroll
        for (int r = 0; r < 8; r++) {
            float4 a = A4[(row0 + r) * 32 + i];
            unsigned long long ax, ay, az, aw;
            SPLAT2(ax, a.x); SPLAT2(ay, a.y); SPLAT2(az, a.z); SPLAT2(aw, a.w);
            FMA2(acc[r][0], ax, b0.x); FMA2(acc[r][1], ax, b0.y);
            FMA2(acc[r][0], ay, b1.x); FMA2(acc[r][1], ay, b1.y);
            FMA2(acc[r][0], az, b2.x); FMA2(acc[r][1], az, b2.y);
            FMA2(acc[r][0], aw, b3.x); FMA2(acc[r][1], aw, b3.y);
        }
    }

    float4 av = ((const float4*)as1)[cg];
    float4 dv = ((const float4*)ad1)[cg];
    uint2* C2 = (uint2*)C;
    float s[8], dd[8];
#pragma unroll
    for (int r = 0; r < 8; r++) {
        float4 c;
        unsigned int lo, hi;
        UNPACK2(lo, hi, acc[r][0]); c.x = __uint_as_float(lo); c.y = __uint_as_float(hi);
        UNPACK2(lo, hi, acc[r][1]); c.z = __uint_as_float(lo); c.w = __uint_as_float(hi);
        half2 p0 = __floats2half2_rn(c.x, c.y);
        half2 p1 = __floats2half2_rn(c.z, c.w);
        uint2 pk;
        pk.x = *(unsigned int*)&p0;
        pk.y = *(unsigned int*)&p1;
        C2[(row0 + r) * 64 + cg] = pk;
        s[r]  = c.x * av.x + c.y * av.y + c.z * av.z + c.w * av.w;
        dd[r] = c.x * dv.x + c.y * dv.y + c.z * dv.z + c.w * dv.w;
    }
#pragma unroll
    for (int o = 1; o < 16; o <<= 1) {
#pragma unroll
        for (int r = 0; r < 8; r++) {
            s[r]  += __shfl_xor_sync(FULL, s[r], o);
            dd[r] += __shfl_xor_sync(FULL, dd[r], o);
        }
    }
    if ((lane & 15) == 0) {
        int head = cg >> 4;
#pragma unroll
        for (int r = 0; r < 8; r++) {
            asrc[(row0 + r) * 4 + head] = s[r];
            adst[(row0 + r) * 4 + head] = dd[r];
        }
    }
}

// ---------------- layer 1 aggregation: single-pass chunked softmax ---------
// Lane l computes the 4 head-weights for edge base+l (4 exps/edge total),
// stages them in smem, denominator accumulated alongside; gather uses
// UNNORMALIZED weights and scales by 1/denom at the end.
__global__ void k_agg1(const int* __restrict__ off, const int* __restrict__ csr,
                       const __half* __restrict__ hfeat, const float* __restrict__ asrc,
                       const float* __restrict__ adst, const float* __restrict__ bias,
                       const float* __restrict__ W2, const float* __restrict__ as2,
                       const float* __restrict__ ad2, __half* __restrict__ h2out,
                       float* __restrict__ asrc2, float* __restrict__ adst2) {
    __shared__ int   sm_s[8][32];
    __shared__ float4 sm_w[8][32];
    int wid = threadIdx.x >> 5;
    int lane = threadIdx.x & 31;
    int d = blockIdx.x * 8 + wid;
    if (d >= NN) return;
    int b0 = off[d], b1 = off[d + 1];

    float4 adv = ((const float4*)adst)[d];
    int hh = lane >> 3;                      // head of this lane (0..3)

    float s0 = 0.f, s1 = 0.f, s2 = 0.f, s3 = 0.f;
    float acc[8];
#pragma unroll
    for (int j = 0; j < 8; j++) acc[j] = 0.f;

    const uint4* hf = (const uint4*)hfeat;
    const float4* as4 = (const float4*)asrc;
    const float* wp = (const float*)&sm_w[wid][0];

    for (int base = b0; base < b1; base += 32) {
        int k = base + lane;
        float4 w = make_float4(0.f, 0.f, 0.f, 0.f);
        int sidx = 0;
        if (k < b1) {
            sidx = csr[k];
            float4 a = as4[sidx];
            w.x = __expf(lrelu(a.x + adv.x));
            w.y = __expf(lrelu(a.y + adv.y));
            w.z = __expf(lrelu(a.z + adv.z));
            w.w = __expf(lrelu(a.w + adv.w));
            s0 += w.x; s1 += w.y; s2 += w.z; s3 += w.w;
        }
        sm_s[wid][lane] = sidx;
        sm_w[wid][lane] = w;
        __syncwarp();
        int cnt = min(32, b1 - base);
        for (int e = 0; e < cnt; e++) {
            int ss = sm_s[wid][e];            // LDS broadcast
            float we = wp[e * 4 + hh];        // LDS, 4 distinct addrs
            uint4 v = hf[ss * 32 + lane];     // 8 halfs: channels 8L..8L+7
            float2 p0 = __half22float2(*(half2*)&v.x);
            float2 p1 = __half22float2(*(half2*)&v.y);
            float2 p2 = __half22float2(*(half2*)&v.z);
            float2 p3 = __half22float2(*(half2*)&v.w);
            acc[0] = fmaf(we, p0.x, acc[0]); acc[1] = fmaf(we, p0.y, acc[1]);
            acc[2] = fmaf(we, p1.x, acc[2]); acc[3] = fmaf(we, p1.y, acc[3]);
            acc[4] = fmaf(we, p2.x, acc[4]); acc[5] = fmaf(we, p2.y, acc[5]);
            acc[6] = fmaf(we, p3.x, acc[6]); acc[7] = fmaf(we, p3.y, acc[7]);
        }
        __syncwarp();
    }

    s0 = warp_sum(s0); s1 = warp_sum(s1); s2 = warp_sum(s2); s3 = warp_sum(s3);
    float iH = (hh == 0) ? 1.f / (s0 + 1e-16f)
             : (hh == 1) ? 1.f / (s1 + 1e-16f)
             : (hh == 2) ? 1.f / (s2 + 1e-16f)
             :             1.f / (s3 + 1e-16f);
#pragma unroll
    for (int j = 0; j < 8; j++) acc[j] *= iH;

    // head mean: channel 8*(lane&7)+j summed over lanes {q, q+8, q+16, q+24}
#pragma unroll
    for (int j = 0; j < 8; j++) {
        acc[j] += __shfl_xor_sync(FULL, acc[j], 8);
        acc[j] += __shfl_xor_sync(FULL, acc[j], 16);
    }
    int cq = lane & 7;
    float4 bb0 = ((const float4*)bias)[cq * 2];
    float4 bb1 = ((const float4*)bias)[cq * 2 + 1];
    float xv[8];
    xv[0] = fmaxf(acc[0] * 0.25f + bb0.x, 0.f);
    xv[1] = fmaxf(acc[1] * 0.25f + bb0.y, 0.f);
    xv[2] = fmaxf(acc[2] * 0.25f + bb0.z, 0.f);
    xv[3] = fmaxf(acc[3] * 0.25f + bb0.w, 0.f);
    xv[4] = fmaxf(acc[4] * 0.25f + bb1.x, 0.f);
    xv[5] = fmaxf(acc[5] * 0.25f + bb1.y, 0.f);
    xv[6] = fmaxf(acc[6] * 0.25f + bb1.z, 0.f);
    xv[7] = fmaxf(acc[7] * 0.25f + bb1.w, 0.f);

    // fused GEMM2: x1[8g+j] lives on lane g; lane computes cols 2L, 2L+1
    const float2* W2f2 = (const float2*)W2;
    float2 h2 = make_float2(0.f, 0.f);
#pragma unroll
    for (int g = 0; g < 8; g++) {
#pragma unroll
        for (int j = 0; j < 8; j++) {
            float v = __shfl_sync(FULL, xv[j], g);
            float2 w = W2f2[(8 * g + j) * 32 + lane];
            h2.x = fmaf(v, w.x, h2.x);
            h2.y = fmaf(v, w.y, h2.y);
        }
    }
    half2 h2h = __floats2half2_rn(h2.x, h2.y);
    ((half2*)h2out)[d * 32 + lane] = h2h;

    // att2: head = lane>>4, channels 2*(lane&15)+{0,1}
    float2 a2 = ((const float2*)as2)[lane];
    float2 d2 = ((const float2*)ad2)[lane];
    float ps = h2.x * a2.x + h2.y * a2.y;
    float pd = h2.x * d2.x + h2.y * d2.y;
#pragma unroll
    for (int o = 1; o < 16; o <<= 1) {
        ps += __shfl_xor_sync(FULL, ps, o);
        pd += __shfl_xor_sync(FULL, pd, o);
    }
    if ((lane & 15) == 0) {
        asrc2[d * 2 + (lane >> 4)] = ps;
        adst2[d * 2 + (lane >> 4)] = pd;
    }
}

// ---------------- layer 2 aggregation: same single-pass scheme + pool ------
__global__ void k_agg2(const int* __restrict__ off, const int* __restrict__ csr,
                       const __half* __restrict__ hfeat, const float* __restrict__ asrc,
                       const float* __restrict__ adst, const float* __restrict__ bias,
                       const int* __restrict__ batch, float* __restrict__ sums,
                       float* __restrict__ gcnt) {
    __shared__ int   sm_s[8][32];
    __shared__ float2 sm_w[8][32];
    int wid = threadIdx.x >> 5;
    int lane = threadIdx.x & 31;
    int d = blockIdx.x * 8 + wid;
    if (d >= NN) return;
    int b0 = off[d], b1 = off[d + 1];

    float2 adv = ((const float2*)adst)[d];
    int hh = lane >> 4;                      // head (0..1)

    float s0 = 0.f, s1 = 0.f;
    float2 acc = make_float2(0.f, 0.f);
    const half2* hf = (const half2*)hfeat;
    const float2* as2p = (const float2*)asrc;
    const float* wp = (const float*)&sm_w[wid][0];

    for (int base = b0; base < b1; base += 32) {
        int k = base + lane;
        float2 w = make_float2(0.f, 0.f);
        int sidx = 0;
        if (k < b1) {
            sidx = csr[k];
            float2 a = as2p[sidx];
            w.x = __expf(lrelu(a.x + adv.x));
            w.y = __expf(lrelu(a.y + adv.y));
            s0 += w.x; s1 += w.y;
        }
        sm_s[wid][lane] = sidx;
        sm_w[wid][lane] = w;
        __syncwarp();
        int cnt = min(32, b1 - base);
        for (int e = 0; e < cnt; e++) {
            int ss = sm_s[wid][e];
            float we = wp[e * 2 + hh];
            float2 v = __half22float2(hf[ss * 32 + lane]);
            acc.x = fmaf(we, v.x, acc.x);
            acc.y = fmaf(we, v.y, acc.y);
        }
        __syncwarp();
    }

    s0 = warp_sum(s0); s1 = warp_sum(s1);
    float iH = hh ? 1.f / (s1 + 1e-16f) : 1.f / (s0 + 1e-16f);
    acc.x *= iH;
    acc.y *= iH;

    acc.x += __shfl_xor_sync(FULL, acc.x, 16);
    acc.y += __shfl_xor_sync(FULL, acc.y, 16);
    if (lane < 16) {
        const float2 b = ((const float2*)bias)[lane];
        float ox = fmaxf(acc.x * 0.5f + b.x, 0.f);
        float oy = fmaxf(acc.y * 0.5f + b.y, 0.f);
        int g = batch[d];
        atomicAdd(&sums[g * 32 + 2 * lane], ox);
        atomicAdd(&sums[g * 32 + 2 * lane + 1], oy);
        if (lane == 0) atomicAdd(&gcnt[g], 1.f);
    }
}

// ---------------- heads ----------------
__global__ void k_heads(const float* __restrict__ sums, const float* __restrict__ cnt,
                        const float* __restrict__ cW1, const float* __restrict__ cb1,
                        const float* __restrict__ cW2, const float* __restrict__ cb2,
                        const float* __restrict__ hW1, const float* __restrict__ hb1,
                        const float* __restrict__ hW2, const float* __restrict__ hb2,
                        float* __restrict__ out) {
    int g = threadIdx.x;
    if (g >= GG) return;
    float emb[32];
    float c_ = cnt[g];
    c_ = (c_ > 1.f) ? c_ : 1.f;
    for (int c = 0; c < 32; c++) emb[c] = sums[g * 32 + c] / c_;
    float oh = hb2[0], oc = cb2[0];
    for (int j = 0; j < 16; j++) {
        float sh = hb1[j], sc = cb1[j];
        for (int c = 0; c < 32; c++) {
            sh = fmaf(emb[c], hW1[c * 16 + j], sh);
            sc = fmaf(emb[c], cW1[c * 16 + j], sc);
        }
        sh = fmaxf(sh, 0.f);
        sc = fmaxf(sc, 0.f);
        oh = fmaf(sh, hW2[j], oh);
        oc = fmaf(sc, cW2[j], oc);
    }
    out[g]      = 1.f / (1.f + __expf(-oh));
    out[GG + g] = 1.f / (1.f + __expf(-oc));
}

// ---------------- host ----------------
static inline int cdiv(long long a, int b) { return (int)((a + b - 1) / b); }

extern "C" void kernel_launch(void* const* d_in, const int* in_sizes, int n_in,
                              void* d_out, int out_size) {
    const float* x     = (const float*)d_in[0];
    const int*   ei    = (const int*)  d_in[1];
    const int*   batch = (const int*)  d_in[2];
    const float* W1  = (const float*)d_in[3];
    const float* as1 = (const float*)d_in[4];
    const float* ad1 = (const float*)d_in[5];
    const float* b1  = (const float*)d_in[6];
    const float* W2  = (const float*)d_in[7];
    const float* as2 = (const float*)d_in[8];
    const float* ad2 = (const float*)d_in[9];
    const float* b2  = (const float*)d_in[10];
    const float* cW1 = (const float*)d_in[11];
    const float* cb1 = (const float*)d_in[12];
    const float* cW2 = (const float*)d_in[13];
    const float* cb2 = (const float*)d_in[14];
    const float* hW1 = (const float*)d_in[15];
    const float* hb1 = (const float*)d_in[16];
    const float* hW2 = (const float*)d_in[17];
    const float* hb2 = (const float*)d_in[18];

    const int* src = ei;
    const int* dst = ei + EE;

    __half *p_h, *p_h2;
    float *p_asrc, *p_adst, *p_asrc2, *p_adst2, *p_sums, *p_gcnt;
    int *p_cnt, *p_off, *p_cur, *p_csr;
    cudaGetSymbolAddress((void**)&p_h, g_h);
    cudaGetSymbolAddress((void**)&p_h2, g_h2);
    cudaGetSymbolAddress((void**)&p_asrc, g_asrc);
    cudaGetSymbolAddress((void**)&p_adst, g_adst);
    cudaGetSymbolAddress((void**)&p_asrc2, g_asrc2);
    cudaGetSymbolAddress((void**)&p_adst2, g_adst2);
    cudaGetSymbolAddress((void**)&p_cnt, g_cnt);
    cudaGetSymbolAddress((void**)&p_off, g_off);
    cudaGetSymbolAddress((void**)&p_cur, g_cur);
    cudaGetSymbolAddress((void**)&p_csr, g_csr);
    cudaGetSymbolAddress((void**)&p_sums, g_sums);
    cudaGetSymbolAddress((void**)&p_gcnt, g_gcnt);

    const int T = 256;

    cudaMemsetAsync(p_cnt, 0, NN * sizeof(int));
    k_gemm1_count<<<GEMM_BLOCKS + COUNT_BLOCKS, T>>>(x, W1, as1, ad1, p_h,
                                                     p_asrc, p_adst, dst, p_cnt);
    k_scan<<<1, 1024>>>(p_cnt, p_off, p_cur, p_sums, p_gcnt);
    k_build<<<cdiv(EE / 4 + NN, T), T>>>(src, dst, p_cur, p_csr);

    k_agg1<<<cdiv(NN, 8), T>>>(p_off, p_csr, p_h, p_asrc, p_adst, b1,
                               W2, as2, ad2, p_h2, p_asrc2, p_adst2);
    k_agg2<<<cdiv(NN, 8), T>>>(p_off, p_csr, p_h2, p_asrc2, p_adst2, b2,
                               batch, p_sums, p_gcnt);
    k_heads<<<1, GG>>>(p_sums, p_gcnt, cW1, cb1, cW2, cb2, hW1, hb1, hW2, hb2,
                       (float*)d_out);
}